// round 10
// baseline (speedup 1.0000x reference)
#include <cuda_runtime.h>
#include <cuda_bf16.h>
#include <cstdint>
#include <math.h>

// ---------------- problem constants ----------------
#define HN     64      // heads
#define PN     64      // head dim
#define GN_    8       // groups
#define NN     128     // state dim
#define CSN    256     // chunk size
#define HIDD   2048
#define INTER  4096    // H*P
#define GNN    1024    // G*N
#define CONVD  6144    // INTER + 2*G*N
#define PROJ   10304   // INTER + CONVD + H
#define LL     2048
#define BB     2
#define TT     4096    // B*L total tokens
#define NCH    16      // total chunks
#define DEADTH (-40.0f)

// ---------------- scratch (__device__ globals; no cudaMalloc allowed) ----------------
__device__ float g_zx   [(size_t)TT * PROJ];                 // in_proj output
__device__ float g_xbc  [(size_t)TT * CONVD];                // conv+silu output
__device__ float g_dt   [(size_t)HN * TT];                   // softplus dt, [h][t]
__device__ float g_dacs [(size_t)HN * TT];                   // per-chunk cumsum dt*A, [h][t]
__device__ float g_cb   [(size_t)NCH * GN_ * CSN * CSN];     // C.B^T per (chunk,group)
__device__ float g_state[(size_t)NCH * HN * PN * NN];
__device__ float g_prev [(size_t)NCH * HN * PN * NN];
__device__ float g_y    [(size_t)TT * INTER];
// tf32-rounded + k-block-permuted GEMM operands
__device__ float g_hr   [(size_t)TT * HIDD];
__device__ float g_w1r  [(size_t)PROJ * HIDD];
__device__ float g_w2r  [(size_t)HIDD * INTER];

// ---------------- helpers ----------------
__device__ __forceinline__ uint32_t f2tf(float x) {
    uint32_t r; asm("cvt.rna.tf32.f32 %0, %1;" : "=r"(r) : "f"(x)); return r;
}
// slot permutation within a 32-float k-block: k -> (k&3)*8 + (k>>3)*2 + ((k>>2)&1)
__device__ __forceinline__ int kslot(int k) {
    return (k & 3) * 8 + (k >> 3) * 2 + ((k >> 2) & 1);
}
__device__ __forceinline__ void mma_tf32(float* c, const uint32_t* a, const uint32_t* b) {
    asm volatile(
        "mma.sync.aligned.m16n8k8.row.col.f32.tf32.tf32.f32 "
        "{%0,%1,%2,%3},{%4,%5,%6,%7},{%8,%9},{%0,%1,%2,%3};\n"
        : "+f"(c[0]), "+f"(c[1]), "+f"(c[2]), "+f"(c[3])
        : "r"(a[0]), "r"(a[1]), "r"(a[2]), "r"(a[3]), "r"(b[0]), "r"(b[1]));
}
__device__ __forceinline__ void cpasync16(uint32_t sdst, const float* gsrc, int srcsz) {
    asm volatile("cp.async.cg.shared.global [%0], [%1], 16, %2;\n"
                 :: "r"(sdst), "l"(gsrc), "r"(srcsz));
}
__device__ __forceinline__ void cpcommit() { asm volatile("cp.async.commit_group;\n"); }
__device__ __forceinline__ void cpwait0()  { asm volatile("cp.async.wait_group 0;\n"); }

__device__ __forceinline__ float siluf(float v) { return v / (1.0f + __expf(-v)); }
__device__ __forceinline__ float softplusf(float x) {
    return (x > 20.0f) ? x : log1pf(__expf(x));
}

// ============================================================
// tf32 GEMM (mma.sync):  C[M,Nn] = A[M,K] * B[Nn,K]^T
// A, B pre-rounded to tf32 AND k-block-permuted (kslot).
// BM=64, BN=256, BK=32. 4 warps of 64x64 (1m x 4n), 128 threads.
// smem 92,160 B/CTA -> 2 CTAs/SM resident: independent barrier domains
// decorrelate LDS bursts and HMMA streams across CTAs on each SMSP.
// ============================================================
#define GPIT 36
#define ASTG (64 * GPIT)
#define BSTG (256 * GPIT)
__global__ __launch_bounds__(128) void k_gemm(
    const float* __restrict__ A, const float* __restrict__ B, float* __restrict__ C,
    int Nn, int nk, int lda, int ldb, int ldc)
{
    extern __shared__ float sm[];
    float* sA = sm;                 // [2][64][GPIT]
    float* sB = sm + 2 * ASTG;      // [2][256][GPIT]

    const int tid  = threadIdx.x;
    const int lane = tid & 31;
    const int warp = tid >> 5;      // 0..3 = n-slab
    const int bm0  = blockIdx.y * 64;
    const int bn0  = blockIdx.x * 256;

    float acc[4][8][4];
#pragma unroll
    for (int i = 0; i < 4; i++)
#pragma unroll
        for (int j = 0; j < 8; j++)
#pragma unroll
            for (int k = 0; k < 4; k++) acc[i][j][k] = 0.0f;

    // stage loader: k-tile kt -> buffer buf (128 threads)
    auto stage = [&](int buf, int kt) {
        int k0 = kt * 32;
        float* sa = sA + buf * ASTG;
        float* sb = sB + buf * BSTG;
        // A: 64 rows x 8 16B-chunks = 512 chunks, 4 iters
#pragma unroll
        for (int i = 0; i < 4; i++) {
            int f = tid + i * 128;
            int r = f >> 3, c4 = (f & 7) * 4;
            const float* ga = A + (size_t)(bm0 + r) * lda + k0 + c4;
            cpasync16((uint32_t)__cvta_generic_to_shared(&sa[r * GPIT + c4]), ga, 16);
        }
        // B: 256 rows x 8 chunks = 2048 chunks, 16 iters
#pragma unroll
        for (int i = 0; i < 16; i++) {
            int f = tid + i * 128;
            int r = f >> 3, c4 = (f & 7) * 4;
            int br = bn0 + r;
            int brc = br < (Nn - 1) ? br : (Nn - 1);
            const float* gb = B + (size_t)brc * ldb + k0 + c4;
            cpasync16((uint32_t)__cvta_generic_to_shared(&sb[r * GPIT + c4]), gb,
                      (br < Nn) ? 16 : 0);
        }
        cpcommit();
    };

    stage(0, 0);

    const int arow = lane >> 2;           // 0..7
    const int kcol = (lane & 3) * 8;      // slot-group base for this lane
    const int kh0  = warp & 1;            // phase stagger within CTA

    for (int kt = 0; kt < nk; kt++) {
        cpwait0();
        __syncthreads();                  // single barrier per k-tile
        if (kt + 1 < nk) stage((kt + 1) & 1, kt + 1);

        const float* a_ = sA + (kt & 1) * ASTG;            // all warps share 64 rows
        const float* b_ = sB + (kt & 1) * BSTG + warp * 64 * GPIT;

#pragma unroll
        for (int khi = 0; khi < 2; khi++) {
            const int kh = khi ^ kh0;
            int co = kcol + kh * 4;
            float4 av[4][2];
#pragma unroll
            for (int mi = 0; mi < 4; mi++) {
                int r0 = mi * 16 + arow;
                av[mi][0] = *(const float4*)&a_[r0 * GPIT + co];
                av[mi][1] = *(const float4*)&a_[(r0 + 8) * GPIT + co];
            }
            float4 bv[8];
#pragma unroll
            for (int ni = 0; ni < 8; ni++) {
                int n0 = ni * 8 + arow;
                bv[ni] = *(const float4*)&b_[n0 * GPIT + co];
            }
#pragma unroll
            for (int q = 0; q < 2; q++) {
#pragma unroll
                for (int mi = 0; mi < 4; mi++) {
                    uint32_t af[4];
                    af[0] = __float_as_uint(q ? av[mi][0].z : av[mi][0].x);
                    af[1] = __float_as_uint(q ? av[mi][1].z : av[mi][1].x);
                    af[2] = __float_as_uint(q ? av[mi][0].w : av[mi][0].y);
                    af[3] = __float_as_uint(q ? av[mi][1].w : av[mi][1].y);
#pragma unroll
                    for (int ni = 0; ni < 8; ni++) {
                        uint32_t bf[2];
                        bf[0] = __float_as_uint(q ? bv[ni].z : bv[ni].x);
                        bf[1] = __float_as_uint(q ? bv[ni].w : bv[ni].y);
                        mma_tf32(acc[mi][ni], af, bf);
                    }
                }
            }
        }
        // no trailing barrier: next iteration's barrier orders buffer reuse
    }

    // epilogue
#pragma unroll
    for (int mi = 0; mi < 4; mi++) {
#pragma unroll
        for (int ni = 0; ni < 8; ni++) {
            int row = bm0 + mi * 16 + arow;
            int col = bn0 + warp * 64 + ni * 8 + (lane & 3) * 2;
            if (col < Nn) {
                *(float2*)&C[(size_t)row * ldc + col] =
                    make_float2(acc[mi][ni][0], acc[mi][ni][1]);
                *(float2*)&C[(size_t)(row + 8) * ldc + col] =
                    make_float2(acc[mi][ni][2], acc[mi][ni][3]);
            }
        }
    }
}

// ============================================================
// tf32-rna round + k-block slot permutation (ld multiple of 32)
// ============================================================
__global__ __launch_bounds__(256) void k_round(
    const float* __restrict__ in, float* __restrict__ out, int n4)
{
    int i = blockIdx.x * 256 + threadIdx.x;
    int stride = gridDim.x * 256;
    for (; i < n4; i += stride) {
        int base = i * 4;
        float4 v = *(const float4*)&in[(size_t)base];
        int blk = base & ~31;
        out[(size_t)(blk | kslot((base + 0) & 31))] = __uint_as_float(f2tf(v.x));
        out[(size_t)(blk | kslot((base + 1) & 31))] = __uint_as_float(f2tf(v.y));
        out[(size_t)(blk | kslot((base + 2) & 31))] = __uint_as_float(f2tf(v.z));
        out[(size_t)(blk | kslot((base + 3) & 31))] = __uint_as_float(f2tf(v.w));
    }
}

// ============================================================
// conv1d (depthwise, causal K=4) + silu over xBC channels
// ============================================================
__global__ __launch_bounds__(256) void k_conv(
    const float* __restrict__ conv_w, const float* __restrict__ conv_b)
{
    int c = blockIdx.x * 256 + threadIdx.x;
    int t = blockIdx.y;
    int lt = t & (LL - 1);
    float w0 = conv_w[c * 4 + 0], w1 = conv_w[c * 4 + 1];
    float w2 = conv_w[c * 4 + 2], w3 = conv_w[c * 4 + 3];
    const float* zp = g_zx + (size_t)t * PROJ + INTER + c;
    float v = conv_b[c];
    if (lt >= 3) v += w0 * zp[-3 * (ptrdiff_t)PROJ];
    if (lt >= 2) v += w1 * zp[-2 * (ptrdiff_t)PROJ];
    if (lt >= 1) v += w2 * zp[-1 * (ptrdiff_t)PROJ];
    v += w3 * zp[0];
    g_xbc[(size_t)t * CONVD + c] = siluf(v);
}

// ============================================================
// dt softplus + per-chunk cumsum of dt*A. grid(16,8), 256 thr
// ============================================================
__global__ __launch_bounds__(256) void k_dtscan(
    const float* __restrict__ A_log, const float* __restrict__ dt_bias)
{
    int warp = threadIdx.x >> 5, lane = threadIdx.x & 31;
    int h = blockIdx.y * 8 + warp;
    int chunk = blockIdx.x;
    float Ah = -__expf(A_log[h]);
    float bias = dt_bias[h];
    int tbase = chunk * CSN + lane * 8;

    float pre[8];
    float run = 0.0f;
    float dts[8];
#pragma unroll
    for (int k = 0; k < 8; k++) {
        float raw = g_zx[(size_t)(tbase + k) * PROJ + (INTER + CONVD) + h];
        float dt = softplusf(raw + bias);
        dts[k] = dt;
        run += dt * Ah;
        pre[k] = run;
    }
    float tot = run;
#pragma unroll
    for (int off = 1; off < 32; off <<= 1) {
        float n = __shfl_up_sync(0xffffffffu, tot, off);
        if (lane >= off) tot += n;
    }
    float excl = tot - run;
#pragma unroll
    for (int k = 0; k < 8; k++) {
        g_dt  [(size_t)h * TT + tbase + k] = dts[k];
        g_dacs[(size_t)h * TT + tbase + k] = pre[k] + excl;
    }
}

// ============================================================
// CB[cg][i][j] = sum_n C[i,n]*B[j,n]   (lower-triangular 64x64 tiles)
// ============================================================
__global__ __launch_bounds__(256) void k_cb()
{
    int tile = blockIdx.x;
    int ti = tile >> 2, tj = tile & 3;
    if (ti < tj) return;
    int cg = blockIdx.y;
    int chunk = cg >> 3, g = cg & 7;

    __shared__ float sC[64][33];
    __shared__ float sB[64][33];

    int tid = threadIdx.x;
    int ty = tid >> 4, tx = tid & 15;
    float acc[4][4];
#pragma unroll
    for (int r = 0; r < 4; r++)
#pragma unroll
        for (int c = 0; c < 4; c++) acc[r][c] = 0.0f;

    const size_t cBase = (size_t)(chunk * CSN) * CONVD + INTER + GNN + (size_t)g * NN;
    const size_t bBase = (size_t)(chunk * CSN) * CONVD + INTER + (size_t)g * NN;

    for (int kt = 0; kt < 4; kt++) {
        int k0 = kt * 32;
#pragma unroll
        for (int i = 0; i < 2; i++) {
            int f = tid + i * 256;
            int r = f >> 3, kv = (f & 7) * 4;
            float4 cv = *(const float4*)&g_xbc[cBase + (size_t)(ti * 64 + r) * CONVD + k0 + kv];
            float4 bv = *(const float4*)&g_xbc[bBase + (size_t)(tj * 64 + r) * CONVD + k0 + kv];
            sC[r][kv + 0] = cv.x; sC[r][kv + 1] = cv.y;
            sC[r][kv + 2] = cv.z; sC[r][kv + 3] = cv.w;
            sB[r][kv + 0] = bv.x; sB[r][kv + 1] = bv.y;
            sB[r][kv + 2] = bv.z; sB[r][kv + 3] = bv.w;
        }
        __syncthreads();
#pragma unroll
        for (int kk = 0; kk < 32; kk++) {
            float a[4], b[4];
#pragma unroll
            for (int r = 0; r < 4; r++) a[r] = sC[ty * 4 + r][kk];
#pragma unroll
            for (int c = 0; c < 4; c++) b[c] = sB[tx * 4 + c][kk];
#pragma unroll
            for (int r = 0; r < 4; r++)
#pragma unroll
                for (int c = 0; c < 4; c++) acc[r][c] += a[r] * b[c];
        }
        __syncthreads();
    }
    float* out = g_cb + (size_t)cg * (CSN * CSN);
#pragma unroll
    for (int r = 0; r < 4; r++) {
        int i = ti * 64 + ty * 4 + r;
        int j = tj * 64 + tx * 4;
        *(float4*)&out[(size_t)i * CSN + j] = make_float4(acc[r][0], acc[r][1], acc[r][2], acc[r][3]);
    }
}

// ============================================================
// Y_diag + D*x  -> g_y.   grid (4 i-tiles, 16 chunks, 64 heads), 256 thr
// ============================================================
__global__ __launch_bounds__(256) void k_ydiag(const float* __restrict__ Dv)
{
    int it = blockIdx.x;
    int chunk = blockIdx.y;
    int h = blockIdx.z;
    int g = h >> 3;
    int i0 = it * 64;
    int tid = threadIdx.x;
    int ty = tid >> 4, tx = tid & 15;
    int p0 = tx * 4;

    __shared__ __align__(16) float sx[32][68];
    __shared__ float sM[32][65];
    __shared__ float sdj[32], sdtj[32], sdi[64];

    const float* dac = g_dacs + (size_t)h * TT + chunk * CSN;
    const float* dtp = g_dt   + (size_t)h * TT + chunk * CSN;
    const float* cbp = g_cb + (size_t)(chunk * 8 + g) * (CSN * CSN);

    if (tid < 64) sdi[tid] = dac[i0 + tid];
    __syncthreads();

    float acc[4][4];
#pragma unroll
    for (int r = 0; r < 4; r++)
#pragma unroll
        for (int c = 0; c < 4; c++) acc[r][c] = 0.0f;

    float dc_i0 = dac[i0];

    for (int jt = 2 * it + 1; jt >= 0; jt--) {
        int j0 = jt * 32;
        bool overlap = (j0 + 32 > i0);
        if (!overlap) {
            float d = dc_i0 - dac[j0 + 31];
            if (d < DEADTH) break;
        }
        if (tid < 32) { sdj[tid] = dac[j0 + tid]; sdtj[tid] = dtp[j0 + tid]; }
        __syncthreads();
#pragma unroll
        for (int i = 0; i < 2; i++) {
            int f = tid + i * 256;
            int j = f >> 4, pv = (f & 15) * 4;
            *(float4*)&sx[j][pv] =
                *(const float4*)&g_xbc[(size_t)(chunk * CSN + j0 + j) * CONVD + h * PN + pv];
        }
        __syncthreads();
        {
            int im = tid >> 2;
            int jb = (tid & 3) * 8;
            float di = sdi[im];
            int gi = i0 + im;
            float4 cb0 = *(const float4*)&cbp[(size_t)gi * CSN + j0 + jb];
            float4 cb1 = *(const float4*)&cbp[(size_t)gi * CSN + j0 + jb + 4];
            float cbv[8] = {cb0.x, cb0.y, cb0.z, cb0.w, cb1.x, cb1.y, cb1.z, cb1.w};
#pragma unroll
            for (int k = 0; k < 8; k++) {
                int j = jb + k;
                int gj = j0 + j;
                float m = 0.0f;
                if (gj <= gi) {
                    float d = fmaxf(di - sdj[j], -80.0f);
                    m = cbv[k] * __expf(d) * sdtj[j];
                }
                sM[j][im] = m;
            }
        }
        __syncthreads();
#pragma unroll 4
        for (int j = 0; j < 32; j++) {
            float4 xv = *(const float4*)&sx[j][p0];
#pragma unroll
            for (int r = 0; r < 4; r++) {
                float m = sM[j][ty * 4 + r];
                acc[r][0] += m * xv.x;
                acc[r][1] += m * xv.y;
                acc[r][2] += m * xv.z;
                acc[r][3] += m * xv.w;
            }
        }
        __syncthreads();
    }

    float Dh = Dv[h];
#pragma unroll
    for (int r = 0; r < 4; r++) {
        int i = i0 + ty * 4 + r;
        int t = chunk * CSN + i;
        float4 xv = *(const float4*)&g_xbc[(size_t)t * CONVD + h * PN + p0];
        float4 o = make_float4(acc[r][0] + Dh * xv.x, acc[r][1] + Dh * xv.y,
                               acc[r][2] + Dh * xv.z, acc[r][3] + Dh * xv.w);
        *(float4*)&g_y[(size_t)t * INTER + h * PN + p0] = o;
    }
}

// ============================================================
// states kernel
// ============================================================
__global__ __launch_bounds__(256) void k_states()
{
    int chunk = blockIdx.x, h = blockIdx.y, g = h >> 3;
    int tid = threadIdx.x;
    int ty = tid >> 4, tx = tid & 15;
    int p0 = ty * 4, n0 = tx * 8;

    __shared__ __align__(16) float sxw[32][68];
    __shared__ __align__(16) float sB[32][132];
    __shared__ float sw[32];

    const float* dac = g_dacs + (size_t)h * TT + chunk * CSN;
    const float* dtp = g_dt   + (size_t)h * TT + chunk * CSN;
    float dlast = dac[CSN - 1];

    float acc[4][8];
#pragma unroll
    for (int r = 0; r < 4; r++)
#pragma unroll
        for (int c = 0; c < 8; c++) acc[r][c] = 0.0f;

    for (int jt = 7; jt >= 0; jt--) {
        int j0 = jt * 32;
        if (dlast - dac[j0 + 31] < DEADTH) break;
        if (tid < 32)
            sw[tid] = __expf(fmaxf(dlast - dac[j0 + tid], -80.0f)) * dtp[j0 + tid];
        __syncthreads();
#pragma unroll
        for (int i = 0; i < 2; i++) {
            int f = tid + i * 256;
            int j = f >> 4, pv = (f & 15) * 4;
            float4 xv = *(const float4*)&g_xbc[(size_t)(chunk * CSN + j0 + j) * CONVD + h * PN + pv];
            float w = sw[j];
            xv.x *= w; xv.y *= w; xv.z *= w; xv.w *= w;
            *(float4*)&sxw[j][pv] = xv;
        }
#pragma unroll
        for (int i = 0; i < 4; i++) {
            int f = tid + i * 256;
            int j = f >> 5, nv = (f & 31) * 4;
            *(float4*)&sB[j][nv] =
                *(const float4*)&g_xbc[(size_t)(chunk * CSN + j0 + j) * CONVD + INTER + g * NN + nv];
        }
        __syncthreads();
#pragma unroll 2
        for (int j = 0; j < 32; j++) {
            float4 xv = *(const float4*)&sxw[j][p0];
            float4 b0 = *(const float4*)&sB[j][n0];
            float4 b1 = *(const float4*)&sB[j][n0 + 4];
            float xr[4] = {xv.x, xv.y, xv.z, xv.w};
            float bb[8] = {b0.x, b0.y, b0.z, b0.w, b1.x, b1.y, b1.z, b1.w};
#pragma unroll
            for (int r = 0; r < 4; r++)
#pragma unroll
                for (int c = 0; c < 8; c++) acc[r][c] += xr[r] * bb[c];
        }
        __syncthreads();
    }

    float* out = g_state + (size_t)(chunk * HN + h) * (PN * NN);
#pragma unroll
    for (int r = 0; r < 4; r++) {
        *(float4*)&out[(size_t)(p0 + r) * NN + n0]     = make_float4(acc[r][0], acc[r][1], acc[r][2], acc[r][3]);
        *(float4*)&out[(size_t)(p0 + r) * NN + n0 + 4] = make_float4(acc[r][4], acc[r][5], acc[r][6], acc[r][7]);
    }
}

// ============================================================
// inter-chunk scan
// ============================================================
__global__ __launch_bounds__(256) void k_scan()
{
    int b = blockIdx.x, h = blockIdx.y;
    int tid = threadIdx.x;
    float acc[32];
#pragma unroll
    for (int k = 0; k < 32; k++) acc[k] = 0.0f;
    for (int cl = 0; cl < 8; cl++) {
        int chunk = b * 8 + cl;
        size_t base = (size_t)(chunk * HN + h) * (PN * NN);
#pragma unroll
        for (int k = 0; k < 32; k++) g_prev[base + tid + k * 256] = acc[k];
        float decay = __expf(fmaxf(g_dacs[(size_t)h * TT + chunk * CSN + CSN - 1], -80.0f));
#pragma unroll
        for (int k = 0; k < 32; k++)
            acc[k] = decay * acc[k] + g_state[base + tid + k * 256];
    }
}

// ============================================================
// Y_off
// ============================================================
__global__ __launch_bounds__(256) void k_yoff()
{
    int chunk = blockIdx.x;
    if ((chunk & 7) == 0) return;
    int h = blockIdx.y, g = h >> 3;
    const float* dac = g_dacs + (size_t)h * TT + chunk * CSN;
    if (dac[0] < DEADTH) return;

    __shared__ __align__(16) float sPT[128][64];
    __shared__ __align__(16) float sC[16][128];

    int tid = threadIdx.x;
    size_t pbase = (size_t)(chunk * HN + h) * (PN * NN);
#pragma unroll
    for (int k = 0; k < 32; k++) {
        int idx = tid + k * 256;
        int p = idx >> 7, n = idx & 127;
        sPT[n][p] = g_prev[pbase + idx];
    }
    __syncthreads();

    int im = tid >> 4;
    int p0 = (tid & 15) * 4;

    for (int it = 0; it < 16; it++) {
        int i0 = it * 16;
        if (dac[i0] < DEADTH) break;
#pragma unroll
        for (int k = 0; k < 2; k++) {
            int f = tid + k * 256;
            int i = f >> 5, nv = (f & 31) * 4;
            *(float4*)&sC[i][nv] =
                *(const float4*)&g_xbc[(size_t)(chunk * CSN + i0 + i) * CONVD + INTER + GNN + g * NN + nv];
        }
        __syncthreads();
        float4 acc = make_float4(0.f, 0.f, 0.f, 0.f);
#pragma unroll 4
        for (int n = 0; n < 128; n++) {
            float cv = sC[im][n];
            float4 pv = *(const float4*)&sPT[n][p0];
            acc.x += cv * pv.x; acc.y += cv * pv.y;
            acc.z += cv * pv.z; acc.w += cv * pv.w;
        }
        float e = __expf(fmaxf(dac[i0 + im], -80.0f));
        int t = chunk * CSN + i0 + im;
        float4 o = *(float4*)&g_y[(size_t)t * INTER + h * PN + p0];
        o.x += e * acc.x; o.y += e * acc.y; o.z += e * acc.z; o.w += e * acc.w;
        *(float4*)&g_y[(size_t)t * INTER + h * PN + p0] = o;
        __syncthreads();
    }
}

// ============================================================
// RMSNorm * silu(z) gate, in place on g_y.
// Output is tf32-rna rounded AND kslot-permuted (GEMM2 A operand).
// ============================================================
__global__ __launch_bounds__(256) void k_norm(const float* __restrict__ norm_w)
{
    int t = blockIdx.x;
    int tid = threadIdx.x;
    __shared__ float red[8];
    float* yp = g_y + (size_t)t * INTER;
    const float* zp = g_zx + (size_t)t * PROJ;

    float ss = 0.0f;
#pragma unroll
    for (int k = 0; k < 16; k++) {
        float v = yp[tid + k * 256];
        ss += v * v;
    }
#pragma unroll
    for (int off = 16; off >= 1; off >>= 1) ss += __shfl_xor_sync(0xffffffffu, ss, off);
    if ((tid & 31) == 0) red[tid >> 5] = ss;
    __syncthreads();
    if (tid == 0) {
        float tot = 0.0f;
#pragma unroll
        for (int i = 0; i < 8; i++) tot += red[i];
        red[0] = rsqrtf(tot * (1.0f / INTER) + 1e-5f);
    }
    __syncthreads();
    float rinv = red[0];
#pragma unroll
    for (int k = 0; k < 16; k++) {
        int c = tid + k * 256;
        float v = yp[c];
        float z = zp[c];
        float o = norm_w[c] * v * rinv * siluf(z);
        yp[(c & ~31) | kslot(c & 31)] = __uint_as_float(f2tf(o));
    }
}

// ============================================================
// launch
// ============================================================
extern "C" void kernel_launch(void* const* d_in, const int* in_sizes, int n_in,
                              void* d_out, int out_size)
{
    const float* hidden   = (const float*)d_in[0];
    const float* in_w     = (const float*)d_in[1];
    const float* conv_w   = (const float*)d_in[2];
    const float* conv_b   = (const float*)d_in[3];
    const float* dt_bias  = (const float*)d_in[4];
    const float* A_log    = (const float*)d_in[5];
    const float* Dv       = (const float*)d_in[6];
    const float* norm_w   = (const float*)d_in[7];
    const float* out_w    = (const float*)d_in[8];
    float* outp = (float*)d_out;

    float* zx;  cudaGetSymbolAddress((void**)&zx,  g_zx);
    float* yy;  cudaGetSymbolAddress((void**)&yy,  g_y);
    float* hr;  cudaGetSymbolAddress((void**)&hr,  g_hr);
    float* w1r; cudaGetSymbolAddress((void**)&w1r, g_w1r);
    float* w2r; cudaGetSymbolAddress((void**)&w2r, g_w2r);

    static int smem_set = 0;
    const int gemm_smem = 2 * (ASTG + BSTG) * (int)sizeof(float);  // 92,160 B
    if (!smem_set) {
        cudaFuncSetAttribute(k_gemm, cudaFuncAttributeMaxDynamicSharedMemorySize, gemm_smem);
        smem_set = 1;
    }

    // 0. pre-round + k-block-permute GEMM operands
    k_round<<<2048, 256>>>(hidden, hr,  (TT * HIDD) / 4);
    k_round<<<4096, 256>>>(in_w,  w1r, (PROJ * HIDD) / 4);
    k_round<<<2048, 256>>>(out_w, w2r, (HIDD * INTER) / 4);

    // 1. in_proj:  zx[T, PROJ] = hr @ w1r^T
    {
        dim3 grid((PROJ + 255) / 256, TT / 64);
        k_gemm<<<grid, 128, gemm_smem>>>(hr, w1r, zx, PROJ, HIDD / 32, HIDD, HIDD, PROJ);
    }
    // 2. conv + silu
    k_conv<<<dim3(CONVD / 256, TT), 256>>>(conv_w, conv_b);
    // 3. dt softplus + cumsum
    k_dtscan<<<dim3(NCH, 8), 256>>>(A_log, dt_bias);
    // 4. CB
    k_cb<<<dim3(16, NCH * GN_), 256>>>();
    // 5. Y_diag + D*x
    k_ydiag<<<dim3(4, NCH, HN), 256>>>(Dv);
    // 6. states
    k_states<<<dim3(NCH, HN), 256>>>();
    // 7. scan
    k_scan<<<dim3(BB, HN), 256>>>();
    // 8. Y_off
    k_yoff<<<dim3(NCH, HN), 256>>>();
    // 9. rmsnorm + gate (writes rounded+permuted y)
    k_norm<<<TT, 256>>>(norm_w);
    // 10. out_proj: out[T, HIDD] = y @ w2r^T
    {
        dim3 grid(HIDD / 256, TT / 64);
        k_gemm<<<grid, 128, gemm_smem>>>(yy, w2r, outp, HIDD, INTER / 32, INTER, INTER, HIDD);
    }
    (void)in_sizes; (void)n_in; (void)out_size;
}

// round 11
// speedup vs baseline: 1.0155x; 1.0155x over previous
#include <cuda_runtime.h>
#include <cuda_bf16.h>
#include <cstdint>
#include <math.h>

// ---------------- problem constants ----------------
#define HN     64      // heads
#define PN     64      // head dim
#define GN_    8       // groups
#define NN     128     // state dim
#define CSN    256     // chunk size
#define HIDD   2048
#define INTER  4096    // H*P
#define GNN    1024    // G*N
#define CONVD  6144    // INTER + 2*G*N
#define PROJ   10304   // INTER + CONVD + H
#define LL     2048
#define BB     2
#define TT     4096    // B*L total tokens
#define NCH    16      // total chunks
#define DEADTH (-40.0f)

// ---------------- scratch (__device__ globals; no cudaMalloc allowed) ----------------
__device__ float g_zx   [(size_t)TT * PROJ];                 // in_proj output
__device__ float g_xbc  [(size_t)TT * CONVD];                // conv+silu output
__device__ float g_dt   [(size_t)HN * TT];                   // softplus dt, [h][t]
__device__ float g_dacs [(size_t)HN * TT];                   // per-chunk cumsum dt*A, [h][t]
__device__ float g_cb   [(size_t)NCH * GN_ * CSN * CSN];     // C.B^T per (chunk,group)
__device__ float g_state[(size_t)NCH * HN * PN * NN];
__device__ float g_prev [(size_t)NCH * HN * PN * NN];
__device__ float g_y    [(size_t)TT * INTER];
// tf32-rounded + k-block-permuted GEMM operands
__device__ float g_hr   [(size_t)TT * HIDD];
__device__ float g_w1r  [(size_t)PROJ * HIDD];
__device__ float g_w2r  [(size_t)HIDD * INTER];

// ---------------- helpers ----------------
__device__ __forceinline__ uint32_t f2tf(float x) {
    uint32_t r; asm("cvt.rna.tf32.f32 %0, %1;" : "=r"(r) : "f"(x)); return r;
}
// slot permutation within a 32-float k-block: k -> (k&3)*8 + (k>>3)*2 + ((k>>2)&1)
__device__ __forceinline__ int kslot(int k) {
    return (k & 3) * 8 + (k >> 3) * 2 + ((k >> 2) & 1);
}
// mma with direct float operands (bit-alias to .b32; no MOV shuffling)
__device__ __forceinline__ void mma4(float* c, float a0, float a1, float a2, float a3,
                                     float b0, float b1) {
    asm volatile(
        "mma.sync.aligned.m16n8k8.row.col.f32.tf32.tf32.f32 "
        "{%0,%1,%2,%3},{%4,%5,%6,%7},{%8,%9},{%0,%1,%2,%3};\n"
        : "+f"(c[0]), "+f"(c[1]), "+f"(c[2]), "+f"(c[3])
        : "r"(__float_as_uint(a0)), "r"(__float_as_uint(a1)),
          "r"(__float_as_uint(a2)), "r"(__float_as_uint(a3)),
          "r"(__float_as_uint(b0)), "r"(__float_as_uint(b1)));
}
__device__ __forceinline__ void cpasync16(uint32_t sdst, const float* gsrc, int srcsz) {
    asm volatile("cp.async.cg.shared.global [%0], [%1], 16, %2;\n"
                 :: "r"(sdst), "l"(gsrc), "r"(srcsz));
}
__device__ __forceinline__ void cpcommit() { asm volatile("cp.async.commit_group;\n"); }

__device__ __forceinline__ float siluf(float v) { return v / (1.0f + __expf(-v)); }
__device__ __forceinline__ float softplusf(float x) {
    return (x > 20.0f) ? x : log1pf(__expf(x));
}

// ============================================================
// tf32 GEMM (mma.sync):  C[M,Nn] = A[M,K] * B[Nn,K]^T
// A, B pre-rounded to tf32 AND k-block-permuted (kslot).
// BM=128, BN=256, BK=32; 8 warps of 64x64; 3-stage cp.async ring.
// Slim issue path: immediate smem offsets, affine global pointers,
// hoisted B-row guard, no fragment-shuffle MOVs.
// ============================================================
#define GPIT 36
#define STGF  (128 * GPIT + 256 * GPIT)      // floats per stage = 13824
#define ASTRIDE_B (32 * GPIT * 4)            // 4608 bytes: 32-row step in A/B regions
__global__ __launch_bounds__(256) void k_gemm(
    const float* __restrict__ A, const float* __restrict__ B, float* __restrict__ C,
    int Nn, int nk, int lda, int ldb, int ldc)
{
    extern __shared__ float sm[];

    const int tid  = threadIdx.x;
    const int lane = tid & 31;
    const int warp = tid >> 5;
    const int wm   = warp >> 2;     // 0..1  (64-row slab)
    const int wn   = warp & 3;      // 0..3  (64-col slab)
    const int bm0  = blockIdx.y * 128;
    const int bn0  = blockIdx.x * 256;

    // ---- loader state (loop-invariant, affine) ----
    const int lr = tid >> 3;              // loader row 0..31 (of each 32-row group)
    const int lc = (tid & 7) * 4;         // loader column (floats)
    uint32_t smbase = (uint32_t)__cvta_generic_to_shared(sm);
    // byte offsets within one stage
    const uint32_t offA0 = (uint32_t)((lr * GPIT + lc) * 4);
    const uint32_t offB0 = (uint32_t)((128 * GPIT + lr * GPIT + lc) * 4);
    const uint32_t sb[3] = { smbase, smbase + STGF * 4, smbase + 2 * STGF * 4 };

    const float* gA = A + (size_t)(bm0 + lr) * lda + lc;
    const bool fastB = (bn0 + 256 <= Nn);
    const float* gB[8];
    int szB[8];
    if (fastB) {
        gB[0] = B + (size_t)(bn0 + lr) * ldb + lc;
    } else {
#pragma unroll
        for (int i = 0; i < 8; i++) {
            int br = bn0 + lr + 32 * i;
            int brc = br < (Nn - 1) ? br : (Nn - 1);
            gB[i] = B + (size_t)brc * ldb + lc;
            szB[i] = (br < Nn) ? 16 : 0;
        }
    }
    const size_t ldb32 = (size_t)32 * ldb;
    const size_t lda32 = (size_t)32 * lda;

    // issue one k-tile into stage s
    auto stage_issue = [&](int s) {
        uint32_t b = sb[s];
#pragma unroll
        for (int i = 0; i < 4; i++)
            cpasync16(b + offA0 + i * ASTRIDE_B, gA + i * lda32, 16);
        if (fastB) {
            const float* g0 = gB[0];
#pragma unroll
            for (int i = 0; i < 8; i++)
                cpasync16(b + offB0 + i * ASTRIDE_B, g0 + i * ldb32, 16);
            gB[0] = g0 + 32;
        } else {
#pragma unroll
            for (int i = 0; i < 8; i++) {
                cpasync16(b + offB0 + i * ASTRIDE_B, gB[i], szB[i]);
                gB[i] += 32;
            }
        }
        cpcommit();
        gA += 32;
    };

    // ---- fragment base pointers (immediate offsets from here) ----
    const int arow = lane >> 2;           // 0..7
    const int kcol = (lane & 3) * 8;      // slot-group base
    const float* aP[3];
    const float* bP[3];
#pragma unroll
    for (int s = 0; s < 3; s++) {
        const float* st = sm + s * STGF;
        aP[s] = st + wm * 64 * GPIT + arow * GPIT + kcol;
        bP[s] = st + 128 * GPIT + wn * 64 * GPIT + arow * GPIT + kcol;
    }

    float acc[4][8][4];
#pragma unroll
    for (int i = 0; i < 4; i++)
#pragma unroll
        for (int j = 0; j < 8; j++)
#pragma unroll
            for (int k = 0; k < 4; k++) acc[i][j][k] = 0.0f;

    stage_issue(0);
    stage_issue(1);

    const float* a0p = aP[0]; const float* a1p = aP[1]; const float* a2p = aP[2];
    const float* b0p = bP[0]; const float* b1p = bP[1]; const float* b2p = bP[2];
    uint32_t s0 = sb[0], s1 = sb[1], s2 = sb[2];

    for (int kt = 0; kt < nk; kt++) {
        if (kt < nk - 1) asm volatile("cp.async.wait_group 1;\n" ::: "memory");
        else             asm volatile("cp.async.wait_group 0;\n" ::: "memory");
        __syncthreads();
        if (kt + 2 < nk) {
            // issue tile kt+2 into ring slot s2
            uint32_t b = s2;
#pragma unroll
            for (int i = 0; i < 4; i++)
                cpasync16(b + offA0 + i * ASTRIDE_B, gA + i * lda32, 16);
            if (fastB) {
                const float* g0 = gB[0];
#pragma unroll
                for (int i = 0; i < 8; i++)
                    cpasync16(b + offB0 + i * ASTRIDE_B, g0 + i * ldb32, 16);
                gB[0] = g0 + 32;
            } else {
#pragma unroll
                for (int i = 0; i < 8; i++) {
                    cpasync16(b + offB0 + i * ASTRIDE_B, gB[i], szB[i]);
                    gB[i] += 32;
                }
            }
            cpcommit();
            gA += 32;
        } else {
            cpcommit();   // keep group count in sync for wait_group
        }

        const float* a_ = a0p;
        const float* b_ = b0p;

#pragma unroll
        for (int kh = 0; kh < 2; kh++) {
            // all offsets compile-time: (mi*16 + {0,8})*GPIT + kh*4
            float4 av[4][2];
#pragma unroll
            for (int mi = 0; mi < 4; mi++) {
                av[mi][0] = *(const float4*)(a_ + (mi * 16 + 0) * GPIT + kh * 4);
                av[mi][1] = *(const float4*)(a_ + (mi * 16 + 8) * GPIT + kh * 4);
            }
            float4 bv[8];
#pragma unroll
            for (int ni = 0; ni < 8; ni++)
                bv[ni] = *(const float4*)(b_ + ni * 8 * GPIT + kh * 4);

#pragma unroll
            for (int mi = 0; mi < 4; mi++) {
#pragma unroll
                for (int ni = 0; ni < 8; ni++) {
                    mma4(acc[mi][ni], av[mi][0].x, av[mi][1].x, av[mi][0].y, av[mi][1].y,
                         bv[ni].x, bv[ni].y);
                }
            }
#pragma unroll
            for (int mi = 0; mi < 4; mi++) {
#pragma unroll
                for (int ni = 0; ni < 8; ni++) {
                    mma4(acc[mi][ni], av[mi][0].z, av[mi][1].z, av[mi][0].w, av[mi][1].w,
                         bv[ni].z, bv[ni].w);
                }
            }
        }

        // rotate ring
        const float* ta = a0p; a0p = a1p; a1p = a2p; a2p = ta;
        const float* tb = b0p; b0p = b1p; b1p = b2p; b2p = tb;
        uint32_t ts = s0; s0 = s1; s1 = s2; s2 = ts;
    }

    // epilogue
#pragma unroll
    for (int mi = 0; mi < 4; mi++) {
#pragma unroll
        for (int ni = 0; ni < 8; ni++) {
            int row = bm0 + wm * 64 + mi * 16 + arow;
            int col = bn0 + wn * 64 + ni * 8 + (lane & 3) * 2;
            if (col < Nn) {
                *(float2*)&C[(size_t)row * ldc + col] =
                    make_float2(acc[mi][ni][0], acc[mi][ni][1]);
                *(float2*)&C[(size_t)(row + 8) * ldc + col] =
                    make_float2(acc[mi][ni][2], acc[mi][ni][3]);
            }
        }
    }
}

// ============================================================
// tf32-rna round + k-block slot permutation (ld multiple of 32)
// ============================================================
__global__ __launch_bounds__(256) void k_round(
    const float* __restrict__ in, float* __restrict__ out, int n4)
{
    int i = blockIdx.x * 256 + threadIdx.x;
    int stride = gridDim.x * 256;
    for (; i < n4; i += stride) {
        int base = i * 4;
        float4 v = *(const float4*)&in[(size_t)base];
        int blk = base & ~31;
        out[(size_t)(blk | kslot((base + 0) & 31))] = __uint_as_float(f2tf(v.x));
        out[(size_t)(blk | kslot((base + 1) & 31))] = __uint_as_float(f2tf(v.y));
        out[(size_t)(blk | kslot((base + 2) & 31))] = __uint_as_float(f2tf(v.z));
        out[(size_t)(blk | kslot((base + 3) & 31))] = __uint_as_float(f2tf(v.w));
    }
}

// ============================================================
// conv1d (depthwise, causal K=4) + silu over xBC channels
// ============================================================
__global__ __launch_bounds__(256) void k_conv(
    const float* __restrict__ conv_w, const float* __restrict__ conv_b)
{
    int c = blockIdx.x * 256 + threadIdx.x;
    int t = blockIdx.y;
    int lt = t & (LL - 1);
    float w0 = conv_w[c * 4 + 0], w1 = conv_w[c * 4 + 1];
    float w2 = conv_w[c * 4 + 2], w3 = conv_w[c * 4 + 3];
    const float* zp = g_zx + (size_t)t * PROJ + INTER + c;
    float v = conv_b[c];
    if (lt >= 3) v += w0 * zp[-3 * (ptrdiff_t)PROJ];
    if (lt >= 2) v += w1 * zp[-2 * (ptrdiff_t)PROJ];
    if (lt >= 1) v += w2 * zp[-1 * (ptrdiff_t)PROJ];
    v += w3 * zp[0];
    g_xbc[(size_t)t * CONVD + c] = siluf(v);
}

// ============================================================
// dt softplus + per-chunk cumsum of dt*A. grid(16,8), 256 thr
// ============================================================
__global__ __launch_bounds__(256) void k_dtscan(
    const float* __restrict__ A_log, const float* __restrict__ dt_bias)
{
    int warp = threadIdx.x >> 5, lane = threadIdx.x & 31;
    int h = blockIdx.y * 8 + warp;
    int chunk = blockIdx.x;
    float Ah = -__expf(A_log[h]);
    float bias = dt_bias[h];
    int tbase = chunk * CSN + lane * 8;

    float pre[8];
    float run = 0.0f;
    float dts[8];
#pragma unroll
    for (int k = 0; k < 8; k++) {
        float raw = g_zx[(size_t)(tbase + k) * PROJ + (INTER + CONVD) + h];
        float dt = softplusf(raw + bias);
        dts[k] = dt;
        run += dt * Ah;
        pre[k] = run;
    }
    float tot = run;
#pragma unroll
    for (int off = 1; off < 32; off <<= 1) {
        float n = __shfl_up_sync(0xffffffffu, tot, off);
        if (lane >= off) tot += n;
    }
    float excl = tot - run;
#pragma unroll
    for (int k = 0; k < 8; k++) {
        g_dt  [(size_t)h * TT + tbase + k] = dts[k];
        g_dacs[(size_t)h * TT + tbase + k] = pre[k] + excl;
    }
}

// ============================================================
// CB[cg][i][j] = sum_n C[i,n]*B[j,n]   (lower-triangular 64x64 tiles)
// ============================================================
__global__ __launch_bounds__(256) void k_cb()
{
    int tile = blockIdx.x;
    int ti = tile >> 2, tj = tile & 3;
    if (ti < tj) return;
    int cg = blockIdx.y;
    int chunk = cg >> 3, g = cg & 7;

    __shared__ float sC[64][33];
    __shared__ float sB[64][33];

    int tid = threadIdx.x;
    int ty = tid >> 4, tx = tid & 15;
    float acc[4][4];
#pragma unroll
    for (int r = 0; r < 4; r++)
#pragma unroll
        for (int c = 0; c < 4; c++) acc[r][c] = 0.0f;

    const size_t cBase = (size_t)(chunk * CSN) * CONVD + INTER + GNN + (size_t)g * NN;
    const size_t bBase = (size_t)(chunk * CSN) * CONVD + INTER + (size_t)g * NN;

    for (int kt = 0; kt < 4; kt++) {
        int k0 = kt * 32;
#pragma unroll
        for (int i = 0; i < 2; i++) {
            int f = tid + i * 256;
            int r = f >> 3, kv = (f & 7) * 4;
            float4 cv = *(const float4*)&g_xbc[cBase + (size_t)(ti * 64 + r) * CONVD + k0 + kv];
            float4 bv = *(const float4*)&g_xbc[bBase + (size_t)(tj * 64 + r) * CONVD + k0 + kv];
            sC[r][kv + 0] = cv.x; sC[r][kv + 1] = cv.y;
            sC[r][kv + 2] = cv.z; sC[r][kv + 3] = cv.w;
            sB[r][kv + 0] = bv.x; sB[r][kv + 1] = bv.y;
            sB[r][kv + 2] = bv.z; sB[r][kv + 3] = bv.w;
        }
        __syncthreads();
#pragma unroll
        for (int kk = 0; kk < 32; kk++) {
            float a[4], b[4];
#pragma unroll
            for (int r = 0; r < 4; r++) a[r] = sC[ty * 4 + r][kk];
#pragma unroll
            for (int c = 0; c < 4; c++) b[c] = sB[tx * 4 + c][kk];
#pragma unroll
            for (int r = 0; r < 4; r++)
#pragma unroll
                for (int c = 0; c < 4; c++) acc[r][c] += a[r] * b[c];
        }
        __syncthreads();
    }
    float* out = g_cb + (size_t)cg * (CSN * CSN);
#pragma unroll
    for (int r = 0; r < 4; r++) {
        int i = ti * 64 + ty * 4 + r;
        int j = tj * 64 + tx * 4;
        *(float4*)&out[(size_t)i * CSN + j] = make_float4(acc[r][0], acc[r][1], acc[r][2], acc[r][3]);
    }
}

// ============================================================
// Y_diag + D*x  -> g_y.   grid (4 i-tiles, 16 chunks, 64 heads), 256 thr
// ============================================================
__global__ __launch_bounds__(256) void k_ydiag(const float* __restrict__ Dv)
{
    int it = blockIdx.x;
    int chunk = blockIdx.y;
    int h = blockIdx.z;
    int g = h >> 3;
    int i0 = it * 64;
    int tid = threadIdx.x;
    int ty = tid >> 4, tx = tid & 15;
    int p0 = tx * 4;

    __shared__ __align__(16) float sx[32][68];
    __shared__ float sM[32][65];
    __shared__ float sdj[32], sdtj[32], sdi[64];

    const float* dac = g_dacs + (size_t)h * TT + chunk * CSN;
    const float* dtp = g_dt   + (size_t)h * TT + chunk * CSN;
    const float* cbp = g_cb + (size_t)(chunk * 8 + g) * (CSN * CSN);

    if (tid < 64) sdi[tid] = dac[i0 + tid];
    __syncthreads();

    float acc[4][4];
#pragma unroll
    for (int r = 0; r < 4; r++)
#pragma unroll
        for (int c = 0; c < 4; c++) acc[r][c] = 0.0f;

    float dc_i0 = dac[i0];

    for (int jt = 2 * it + 1; jt >= 0; jt--) {
        int j0 = jt * 32;
        bool overlap = (j0 + 32 > i0);
        if (!overlap) {
            float d = dc_i0 - dac[j0 + 31];
            if (d < DEADTH) break;
        }
        if (tid < 32) { sdj[tid] = dac[j0 + tid]; sdtj[tid] = dtp[j0 + tid]; }
        __syncthreads();
#pragma unroll
        for (int i = 0; i < 2; i++) {
            int f = tid + i * 256;
            int j = f >> 4, pv = (f & 15) * 4;
            *(float4*)&sx[j][pv] =
                *(const float4*)&g_xbc[(size_t)(chunk * CSN + j0 + j) * CONVD + h * PN + pv];
        }
        __syncthreads();
        {
            int im = tid >> 2;
            int jb = (tid & 3) * 8;
            float di = sdi[im];
            int gi = i0 + im;
            float4 cb0 = *(const float4*)&cbp[(size_t)gi * CSN + j0 + jb];
            float4 cb1 = *(const float4*)&cbp[(size_t)gi * CSN + j0 + jb + 4];
            float cbv[8] = {cb0.x, cb0.y, cb0.z, cb0.w, cb1.x, cb1.y, cb1.z, cb1.w};
#pragma unroll
            for (int k = 0; k < 8; k++) {
                int j = jb + k;
                int gj = j0 + j;
                float m = 0.0f;
                if (gj <= gi) {
                    float d = fmaxf(di - sdj[j], -80.0f);
                    m = cbv[k] * __expf(d) * sdtj[j];
                }
                sM[j][im] = m;
            }
        }
        __syncthreads();
#pragma unroll 4
        for (int j = 0; j < 32; j++) {
            float4 xv = *(const float4*)&sx[j][p0];
#pragma unroll
            for (int r = 0; r < 4; r++) {
                float m = sM[j][ty * 4 + r];
                acc[r][0] += m * xv.x;
                acc[r][1] += m * xv.y;
                acc[r][2] += m * xv.z;
                acc[r][3] += m * xv.w;
            }
        }
        __syncthreads();
    }

    float Dh = Dv[h];
#pragma unroll
    for (int r = 0; r < 4; r++) {
        int i = i0 + ty * 4 + r;
        int t = chunk * CSN + i;
        float4 xv = *(const float4*)&g_xbc[(size_t)t * CONVD + h * PN + p0];
        float4 o = make_float4(acc[r][0] + Dh * xv.x, acc[r][1] + Dh * xv.y,
                               acc[r][2] + Dh * xv.z, acc[r][3] + Dh * xv.w);
        *(float4*)&g_y[(size_t)t * INTER + h * PN + p0] = o;
    }
}

// ============================================================
// states kernel
// ============================================================
__global__ __launch_bounds__(256) void k_states()
{
    int chunk = blockIdx.x, h = blockIdx.y, g = h >> 3;
    int tid = threadIdx.x;
    int ty = tid >> 4, tx = tid & 15;
    int p0 = ty * 4, n0 = tx * 8;

    __shared__ __align__(16) float sxw[32][68];
    __shared__ __align__(16) float sB[32][132];
    __shared__ float sw[32];

    const float* dac = g_dacs + (size_t)h * TT + chunk * CSN;
    const float* dtp = g_dt   + (size_t)h * TT + chunk * CSN;
    float dlast = dac[CSN - 1];

    float acc[4][8];
#pragma unroll
    for (int r = 0; r < 4; r++)
#pragma unroll
        for (int c = 0; c < 8; c++) acc[r][c] = 0.0f;

    for (int jt = 7; jt >= 0; jt--) {
        int j0 = jt * 32;
        if (dlast - dac[j0 + 31] < DEADTH) break;
        if (tid < 32)
            sw[tid] = __expf(fmaxf(dlast - dac[j0 + tid], -80.0f)) * dtp[j0 + tid];
        __syncthreads();
#pragma unroll
        for (int i = 0; i < 2; i++) {
            int f = tid + i * 256;
            int j = f >> 4, pv = (f & 15) * 4;
            float4 xv = *(const float4*)&g_xbc[(size_t)(chunk * CSN + j0 + j) * CONVD + h * PN + pv];
            float w = sw[j];
            xv.x *= w; xv.y *= w; xv.z *= w; xv.w *= w;
            *(float4*)&sxw[j][pv] = xv;
        }
#pragma unroll
        for (int i = 0; i < 4; i++) {
            int f = tid + i * 256;
            int j = f >> 5, nv = (f & 31) * 4;
            *(float4*)&sB[j][nv] =
                *(const float4*)&g_xbc[(size_t)(chunk * CSN + j0 + j) * CONVD + INTER + g * NN + nv];
        }
        __syncthreads();
#pragma unroll 2
        for (int j = 0; j < 32; j++) {
            float4 xv = *(const float4*)&sxw[j][p0];
            float4 b0 = *(const float4*)&sB[j][n0];
            float4 b1 = *(const float4*)&sB[j][n0 + 4];
            float xr[4] = {xv.x, xv.y, xv.z, xv.w};
            float bb[8] = {b0.x, b0.y, b0.z, b0.w, b1.x, b1.y, b1.z, b1.w};
#pragma unroll
            for (int r = 0; r < 4; r++)
#pragma unroll
                for (int c = 0; c < 8; c++) acc[r][c] += xr[r] * bb[c];
        }
        __syncthreads();
    }

    float* out = g_state + (size_t)(chunk * HN + h) * (PN * NN);
#pragma unroll
    for (int r = 0; r < 4; r++) {
        *(float4*)&out[(size_t)(p0 + r) * NN + n0]     = make_float4(acc[r][0], acc[r][1], acc[r][2], acc[r][3]);
        *(float4*)&out[(size_t)(p0 + r) * NN + n0 + 4] = make_float4(acc[r][4], acc[r][5], acc[r][6], acc[r][7]);
    }
}

// ============================================================
// inter-chunk scan
// ============================================================
__global__ __launch_bounds__(256) void k_scan()
{
    int b = blockIdx.x, h = blockIdx.y;
    int tid = threadIdx.x;
    float acc[32];
#pragma unroll
    for (int k = 0; k < 32; k++) acc[k] = 0.0f;
    for (int cl = 0; cl < 8; cl++) {
        int chunk = b * 8 + cl;
        size_t base = (size_t)(chunk * HN + h) * (PN * NN);
#pragma unroll
        for (int k = 0; k < 32; k++) g_prev[base + tid + k * 256] = acc[k];
        float decay = __expf(fmaxf(g_dacs[(size_t)h * TT + chunk * CSN + CSN - 1], -80.0f));
#pragma unroll
        for (int k = 0; k < 32; k++)
            acc[k] = decay * acc[k] + g_state[base + tid + k * 256];
    }
}

// ============================================================
// Y_off
// ============================================================
__global__ __launch_bounds__(256) void k_yoff()
{
    int chunk = blockIdx.x;
    if ((chunk & 7) == 0) return;
    int h = blockIdx.y, g = h >> 3;
    const float* dac = g_dacs + (size_t)h * TT + chunk * CSN;
    if (dac[0] < DEADTH) return;

    __shared__ __align__(16) float sPT[128][64];
    __shared__ __align__(16) float sC[16][128];

    int tid = threadIdx.x;
    size_t pbase = (size_t)(chunk * HN + h) * (PN * NN);
#pragma unroll
    for (int k = 0; k < 32; k++) {
        int idx = tid + k * 256;
        int p = idx >> 7, n = idx & 127;
        sPT[n][p] = g_prev[pbase + idx];
    }
    __syncthreads();

    int im = tid >> 4;
    int p0 = (tid & 15) * 4;

    for (int it = 0; it < 16; it++) {
        int i0 = it * 16;
        if (dac[i0] < DEADTH) break;
#pragma unroll
        for (int k = 0; k < 2; k++) {
            int f = tid + k * 256;
            int i = f >> 5, nv = (f & 31) * 4;
            *(float4*)&sC[i][nv] =
                *(const float4*)&g_xbc[(size_t)(chunk * CSN + i0 + i) * CONVD + INTER + GNN + g * NN + nv];
        }
        __syncthreads();
        float4 acc = make_float4(0.f, 0.f, 0.f, 0.f);
#pragma unroll 4
        for (int n = 0; n < 128; n++) {
            float cv = sC[im][n];
            float4 pv = *(const float4*)&sPT[n][p0];
            acc.x += cv * pv.x; acc.y += cv * pv.y;
            acc.z += cv * pv.z; acc.w += cv * pv.w;
        }
        float e = __expf(fmaxf(dac[i0 + im], -80.0f));
        int t = chunk * CSN + i0 + im;
        float4 o = *(float4*)&g_y[(size_t)t * INTER + h * PN + p0];
        o.x += e * acc.x; o.y += e * acc.y; o.z += e * acc.z; o.w += e * acc.w;
        *(float4*)&g_y[(size_t)t * INTER + h * PN + p0] = o;
        __syncthreads();
    }
}

// ============================================================
// RMSNorm * silu(z) gate, in place on g_y.
// Output is tf32-rna rounded AND kslot-permuted (GEMM2 A operand).
// ============================================================
__global__ __launch_bounds__(256) void k_norm(const float* __restrict__ norm_w)
{
    int t = blockIdx.x;
    int tid = threadIdx.x;
    __shared__ float red[8];
    float* yp = g_y + (size_t)t * INTER;
    const float* zp = g_zx + (size_t)t * PROJ;

    float ss = 0.0f;
#pragma unroll
    for (int k = 0; k < 16; k++) {
        float v = yp[tid + k * 256];
        ss += v * v;
    }
#pragma unroll
    for (int off = 16; off >= 1; off >>= 1) ss += __shfl_xor_sync(0xffffffffu, ss, off);
    if ((tid & 31) == 0) red[tid >> 5] = ss;
    __syncthreads();
    if (tid == 0) {
        float tot = 0.0f;
#pragma unroll
        for (int i = 0; i < 8; i++) tot += red[i];
        red[0] = rsqrtf(tot * (1.0f / INTER) + 1e-5f);
    }
    __syncthreads();
    float rinv = red[0];
#pragma unroll
    for (int k = 0; k < 16; k++) {
        int c = tid + k * 256;
        float v = yp[c];
        float z = zp[c];
        float o = norm_w[c] * v * rinv * siluf(z);
        yp[(c & ~31) | kslot(c & 31)] = __uint_as_float(f2tf(o));
    }
}

// ============================================================
// launch
// ============================================================
extern "C" void kernel_launch(void* const* d_in, const int* in_sizes, int n_in,
                              void* d_out, int out_size)
{
    const float* hidden   = (const float*)d_in[0];
    const float* in_w     = (const float*)d_in[1];
    const float* conv_w   = (const float*)d_in[2];
    const float* conv_b   = (const float*)d_in[3];
    const float* dt_bias  = (const float*)d_in[4];
    const float* A_log    = (const float*)d_in[5];
    const float* Dv       = (const float*)d_in[6];
    const float* norm_w   = (const float*)d_in[7];
    const float* out_w    = (const float*)d_in[8];
    float* outp = (float*)d_out;

    float* zx;  cudaGetSymbolAddress((void**)&zx,  g_zx);
    float* yy;  cudaGetSymbolAddress((void**)&yy,  g_y);
    float* hr;  cudaGetSymbolAddress((void**)&hr,  g_hr);
    float* w1r; cudaGetSymbolAddress((void**)&w1r, g_w1r);
    float* w2r; cudaGetSymbolAddress((void**)&w2r, g_w2r);

    static int smem_set = 0;
    const int gemm_smem = 3 * STGF * (int)sizeof(float);  // 165,888 B
    if (!smem_set) {
        cudaFuncSetAttribute(k_gemm, cudaFuncAttributeMaxDynamicSharedMemorySize, gemm_smem);
        smem_set = 1;
    }

    // 0. pre-round + k-block-permute GEMM operands
    k_round<<<2048, 256>>>(hidden, hr,  (TT * HIDD) / 4);
    k_round<<<4096, 256>>>(in_w,  w1r, (PROJ * HIDD) / 4);
    k_round<<<2048, 256>>>(out_w, w2r, (HIDD * INTER) / 4);

    // 1. in_proj:  zx[T, PROJ] = hr @ w1r^T
    {
        dim3 grid((PROJ + 255) / 256, TT / 128);
        k_gemm<<<grid, 256, gemm_smem>>>(hr, w1r, zx, PROJ, HIDD / 32, HIDD, HIDD, PROJ);
    }
    // 2. conv + silu
    k_conv<<<dim3(CONVD / 256, TT), 256>>>(conv_w, conv_b);
    // 3. dt softplus + cumsum
    k_dtscan<<<dim3(NCH, 8), 256>>>(A_log, dt_bias);
    // 4. CB
    k_cb<<<dim3(16, NCH * GN_), 256>>>();
    // 5. Y_diag + D*x
    k_ydiag<<<dim3(4, NCH, HN), 256>>>(Dv);
    // 6. states
    k_states<<<dim3(NCH, HN), 256>>>();
    // 7. scan
    k_scan<<<dim3(BB, HN), 256>>>();
    // 8. Y_off
    k_yoff<<<dim3(NCH, HN), 256>>>();
    // 9. rmsnorm + gate (writes rounded+permuted y)
    k_norm<<<TT, 256>>>(norm_w);
    // 10. out_proj: out[T, HIDD] = y @ w2r^T
    {
        dim3 grid(HIDD / 256, TT / 128);
        k_gemm<<<grid, 256, gemm_smem>>>(yy, w2r, outp, HIDD, INTER / 32, INTER, INTER, HIDD);
    }
    (void)in_sizes; (void)n_in; (void)out_size;
}

// round 15
// speedup vs baseline: 1.3344x; 1.3141x over previous
#include <cuda_runtime.h>
#include <cuda_fp16.h>
#include <cstdint>
#include <math.h>

// ---------------- problem constants ----------------
#define HN     64      // heads
#define PN     64      // head dim
#define GN_    8       // groups
#define NN     128     // state dim
#define CSN    256     // chunk size
#define HIDD   2048
#define INTER  4096    // H*P
#define GNN    1024    // G*N
#define CONVD  6144    // INTER + 2*G*N
#define PROJ   10304   // INTER + CONVD + H
#define LL     2048
#define BB     2
#define TT     4096    // B*L total tokens
#define NCH    16      // total chunks
#define DEADTH (-40.0f)

// ---------------- scratch (__device__ globals; no cudaMalloc allowed) ----------------
__device__ float g_zx   [(size_t)TT * PROJ];                 // in_proj output
__device__ float g_xbc  [(size_t)TT * CONVD];                // conv+silu output
__device__ float g_dt   [(size_t)HN * TT];                   // softplus dt, [h][t]
__device__ float g_dacs [(size_t)HN * TT];                   // per-chunk cumsum dt*A, [h][t]
__device__ float g_cb   [(size_t)NCH * GN_ * CSN * CSN];     // C.B^T per (chunk,group)
__device__ float g_state[(size_t)NCH * HN * PN * NN];
__device__ float g_prev [(size_t)NCH * HN * PN * NN];
__device__ float g_y    [(size_t)TT * INTER];
// fp16 GEMM operands (k-block permuted for m16n8k16 fragments)
__device__ __half g_ha  [(size_t)TT * HIDD];
__device__ __half g_w1h [(size_t)PROJ * HIDD];
__device__ __half g_w2h [(size_t)HIDD * INTER];
__device__ __half g_yh  [(size_t)TT * INTER];

// ---------------- helpers ----------------
// k permutation within a 32-k block for m16n8k16 fragments:
// lane t (=k-quad) reads halves [t*8, t*8+8) = uint4 covering both k16 blocks.
__device__ __host__ __forceinline__ int kperm(int k) {
    return ((k >> 1) & 3) * 8 + ((k >> 4) & 1) * 4 + ((k >> 3) & 1) * 2 + (k & 1);
}
__device__ __forceinline__ void mmah(float* c, uint32_t a0, uint32_t a1, uint32_t a2,
                                     uint32_t a3, uint32_t b0, uint32_t b1) {
    asm volatile(
        "mma.sync.aligned.m16n8k16.row.col.f32.f16.f16.f32 "
        "{%0,%1,%2,%3},{%4,%5,%6,%7},{%8,%9},{%0,%1,%2,%3};\n"
        : "+f"(c[0]), "+f"(c[1]), "+f"(c[2]), "+f"(c[3])
        : "r"(a0), "r"(a1), "r"(a2), "r"(a3), "r"(b0), "r"(b1));
}
__device__ __forceinline__ void cpasync16(uint32_t sdst, const void* gsrc, int srcsz) {
    asm volatile("cp.async.cg.shared.global [%0], [%1], 16, %2;\n"
                 :: "r"(sdst), "l"(gsrc), "r"(srcsz));
}
__device__ __forceinline__ void cpcommit() { asm volatile("cp.async.commit_group;\n"); }

__device__ __forceinline__ float siluf(float v) { return v / (1.0f + __expf(-v)); }
__device__ __forceinline__ float softplusf(float x) {
    return (x > 20.0f) ? x : log1pf(__expf(x));
}

// ============================================================
// fp16 GEMM (mma.sync.m16n8k16):  C[M,Nn] = A[M,K] * B[Nn,K]^T
// A, B fp16, k-block permuted (kperm). BM=128, BN=256, BK=32.
// 8 warps of 64x64; 3-stage cp.async ring; fp32 accumulate.
// smem row pitch 40 halves (80 B); stage = 30720 B.
// ============================================================
#define STGB 30720
__global__ __launch_bounds__(256) void k_gemm(
    const __half* __restrict__ A, const __half* __restrict__ B, float* __restrict__ C,
    int Nn, int nk, int lda, int ldb, int ldc)
{
    extern __shared__ char smc[];

    const int tid  = threadIdx.x;
    const int lane = tid & 31;
    const int warp = tid >> 5;
    const int wm   = warp >> 2;     // 0..1
    const int wn   = warp & 3;      // 0..3
    const int bm0  = blockIdx.y * 128;
    const int bn0  = blockIdx.x * 256;

    // ---- loader (affine) ----
    const int lr  = tid >> 2;       // 0..63
    const int lch = tid & 3;        // 16B chunk within 64B row-block
    const uint32_t smb = (uint32_t)__cvta_generic_to_shared(smc);
    const uint32_t offA = (uint32_t)(lr * 80 + lch * 16);
    const uint32_t offB = (uint32_t)(10240 + lr * 80 + lch * 16);

    const __half* gA = A + (size_t)(bm0 + lr) * lda + lch * 8;
    const size_t ldaS = (size_t)64 * lda;
    const size_t ldbS = (size_t)64 * ldb;
    const bool fastB = (bn0 + 256 <= Nn);
    const __half* gB[4]; int szB[4];
    if (fastB) {
        gB[0] = B + (size_t)(bn0 + lr) * ldb + lch * 8;
    } else {
#pragma unroll
        for (int i = 0; i < 4; i++) {
            int br = bn0 + lr + 64 * i;
            int brc = br < (Nn - 1) ? br : (Nn - 1);
            gB[i] = B + (size_t)brc * ldb + lch * 8;
            szB[i] = (br < Nn) ? 16 : 0;
        }
    }

    float acc[4][8][4];
#pragma unroll
    for (int i = 0; i < 4; i++)
#pragma unroll
        for (int j = 0; j < 8; j++)
#pragma unroll
            for (int k = 0; k < 4; k++) acc[i][j][k] = 0.0f;

    // fragment base pointers per stage
    const int g = lane >> 2, t = lane & 3;
    const char* aP0 = smc + (wm * 64 + g) * 80 + t * 16;
    const char* bP0 = smc + 10240 + (wn * 64 + g) * 80 + t * 16;

    uint32_t s0 = smb, s1 = smb + STGB, s2 = smb + 2 * STGB;
    const char* a0p = aP0;            const char* a1p = aP0 + STGB; const char* a2p = aP0 + 2 * STGB;
    const char* b0p = bP0;            const char* b1p = bP0 + STGB; const char* b2p = bP0 + 2 * STGB;

    // issue one k-tile into ring slot at smem base sbb
    auto issue = [&](uint32_t sbb) {
        cpasync16(sbb + offA,            gA, 16);
        cpasync16(sbb + offA + 64 * 80,  gA + ldaS, 16);
        if (fastB) {
            const __half* g0 = gB[0];
#pragma unroll
            for (int i = 0; i < 4; i++)
                cpasync16(sbb + offB + i * 64 * 80, g0 + i * ldbS, 16);
            gB[0] = g0 + 32;
        } else {
#pragma unroll
            for (int i = 0; i < 4; i++) {
                cpasync16(sbb + offB + i * 64 * 80, gB[i], szB[i]);
                gB[i] += 32;
            }
        }
        cpcommit();
        gA += 32;
    };

    issue(s0);
    issue(s1);

    for (int kt = 0; kt < nk; kt++) {
        if (kt < nk - 1) asm volatile("cp.async.wait_group 1;\n" ::: "memory");
        else             asm volatile("cp.async.wait_group 0;\n" ::: "memory");
        __syncthreads();
        if (kt + 2 < nk) issue(s2);
        else             cpcommit();          // keep group count aligned

        const char* a_ = a0p;
        const char* b_ = b0p;

        uint4 av0[4], av1[4], bv[8];
#pragma unroll
        for (int mi = 0; mi < 4; mi++) {
            av0[mi] = *(const uint4*)(a_ + mi * 1280);         // row mi*16+g
            av1[mi] = *(const uint4*)(a_ + mi * 1280 + 640);   // row mi*16+8+g
        }
#pragma unroll
        for (int ni = 0; ni < 8; ni++)
            bv[ni] = *(const uint4*)(b_ + ni * 640);           // col ni*8+g

        // k16 block 0: .x/.y halves ; block 1: .z/.w
#pragma unroll
        for (int mi = 0; mi < 4; mi++)
#pragma unroll
            for (int ni = 0; ni < 8; ni++)
                mmah(acc[mi][ni], av0[mi].x, av1[mi].x, av0[mi].y, av1[mi].y,
                     bv[ni].x, bv[ni].y);
#pragma unroll
        for (int mi = 0; mi < 4; mi++)
#pragma unroll
            for (int ni = 0; ni < 8; ni++)
                mmah(acc[mi][ni], av0[mi].z, av1[mi].z, av0[mi].w, av1[mi].w,
                     bv[ni].z, bv[ni].w);

        // rotate ring
        uint32_t ts = s0; s0 = s1; s1 = s2; s2 = ts;
        const char* ta = a0p; a0p = a1p; a1p = a2p; a2p = ta;
        const char* tb = b0p; b0p = b1p; b1p = b2p; b2p = tb;
    }

    // epilogue (same fp32 C-fragment layout as m16n8 tf32)
#pragma unroll
    for (int mi = 0; mi < 4; mi++) {
#pragma unroll
        for (int ni = 0; ni < 8; ni++) {
            int row = bm0 + wm * 64 + mi * 16 + g;
            int col = bn0 + wn * 64 + ni * 8 + t * 2;
            if (col < Nn) {
                *(float2*)&C[(size_t)row * ldc + col] =
                    make_float2(acc[mi][ni][0], acc[mi][ni][1]);
                *(float2*)&C[(size_t)(row + 8) * ldc + col] =
                    make_float2(acc[mi][ni][2], acc[mi][ni][3]);
            }
        }
    }
}

// ============================================================
// float -> fp16 conversion with k-block permutation
// ============================================================
__global__ __launch_bounds__(256) void k_cvt(
    const float* __restrict__ in, __half* __restrict__ out, int n4)
{
    int i = blockIdx.x * 256 + threadIdx.x;
    int stride = gridDim.x * 256;
    for (; i < n4; i += stride) {
        int base = i * 4;
        float4 v = *(const float4*)&in[(size_t)base];
        int blk = base & ~31;
        out[(size_t)(blk | kperm((base + 0) & 31))] = __float2half_rn(v.x);
        out[(size_t)(blk | kperm((base + 1) & 31))] = __float2half_rn(v.y);
        out[(size_t)(blk | kperm((base + 2) & 31))] = __float2half_rn(v.z);
        out[(size_t)(blk | kperm((base + 3) & 31))] = __float2half_rn(v.w);
    }
}

// ============================================================
// conv1d (depthwise, causal K=4) + silu over xBC channels
// ============================================================
__global__ __launch_bounds__(256) void k_conv(
    const float* __restrict__ conv_w, const float* __restrict__ conv_b)
{
    int c = blockIdx.x * 256 + threadIdx.x;
    int t = blockIdx.y;
    int lt = t & (LL - 1);
    float w0 = conv_w[c * 4 + 0], w1 = conv_w[c * 4 + 1];
    float w2 = conv_w[c * 4 + 2], w3 = conv_w[c * 4 + 3];
    const float* zp = g_zx + (size_t)t * PROJ + INTER + c;
    float v = conv_b[c];
    if (lt >= 3) v += w0 * zp[-3 * (ptrdiff_t)PROJ];
    if (lt >= 2) v += w1 * zp[-2 * (ptrdiff_t)PROJ];
    if (lt >= 1) v += w2 * zp[-1 * (ptrdiff_t)PROJ];
    v += w3 * zp[0];
    g_xbc[(size_t)t * CONVD + c] = siluf(v);
}

// ============================================================
// dt softplus + per-chunk cumsum of dt*A. grid(16,8), 256 thr
// ============================================================
__global__ __launch_bounds__(256) void k_dtscan(
    const float* __restrict__ A_log, const float* __restrict__ dt_bias)
{
    int warp = threadIdx.x >> 5, lane = threadIdx.x & 31;
    int h = blockIdx.y * 8 + warp;
    int chunk = blockIdx.x;
    float Ah = -__expf(A_log[h]);
    float bias = dt_bias[h];
    int tbase = chunk * CSN + lane * 8;

    float pre[8];
    float run = 0.0f;
    float dts[8];
#pragma unroll
    for (int k = 0; k < 8; k++) {
        float raw = g_zx[(size_t)(tbase + k) * PROJ + (INTER + CONVD) + h];
        float dt = softplusf(raw + bias);
        dts[k] = dt;
        run += dt * Ah;
        pre[k] = run;
    }
    float tot = run;
#pragma unroll
    for (int off = 1; off < 32; off <<= 1) {
        float n = __shfl_up_sync(0xffffffffu, tot, off);
        if (lane >= off) tot += n;
    }
    float excl = tot - run;
#pragma unroll
    for (int k = 0; k < 8; k++) {
        g_dt  [(size_t)h * TT + tbase + k] = dts[k];
        g_dacs[(size_t)h * TT + tbase + k] = pre[k] + excl;
    }
}

// ============================================================
// CB[cg][i][j] = sum_n C[i,n]*B[j,n]   (lower-triangular 64x64 tiles)
// ============================================================
__global__ __launch_bounds__(256) void k_cb()
{
    int tile = blockIdx.x;
    int ti = tile >> 2, tj = tile & 3;
    if (ti < tj) return;
    int cg = blockIdx.y;
    int chunk = cg >> 3, g = cg & 7;

    __shared__ float sC[64][33];
    __shared__ float sB[64][33];

    int tid = threadIdx.x;
    int ty = tid >> 4, tx = tid & 15;
    float acc[4][4];
#pragma unroll
    for (int r = 0; r < 4; r++)
#pragma unroll
        for (int c = 0; c < 4; c++) acc[r][c] = 0.0f;

    const size_t cBase = (size_t)(chunk * CSN) * CONVD + INTER + GNN + (size_t)g * NN;
    const size_t bBase = (size_t)(chunk * CSN) * CONVD + INTER + (size_t)g * NN;

    for (int kt = 0; kt < 4; kt++) {
        int k0 = kt * 32;
#pragma unroll
        for (int i = 0; i < 2; i++) {
            int f = tid + i * 256;
            int r = f >> 3, kv = (f & 7) * 4;
            float4 cv = *(const float4*)&g_xbc[cBase + (size_t)(ti * 64 + r) * CONVD + k0 + kv];
            float4 bv = *(const float4*)&g_xbc[bBase + (size_t)(tj * 64 + r) * CONVD + k0 + kv];
            sC[r][kv + 0] = cv.x; sC[r][kv + 1] = cv.y;
            sC[r][kv + 2] = cv.z; sC[r][kv + 3] = cv.w;
            sB[r][kv + 0] = bv.x; sB[r][kv + 1] = bv.y;
            sB[r][kv + 2] = bv.z; sB[r][kv + 3] = bv.w;
        }
        __syncthreads();
#pragma unroll
        for (int kk = 0; kk < 32; kk++) {
            float a[4], b[4];
#pragma unroll
            for (int r = 0; r < 4; r++) a[r] = sC[ty * 4 + r][kk];
#pragma unroll
            for (int c = 0; c < 4; c++) b[c] = sB[tx * 4 + c][kk];
#pragma unroll
            for (int r = 0; r < 4; r++)
#pragma unroll
                for (int c = 0; c < 4; c++) acc[r][c] += a[r] * b[c];
        }
        __syncthreads();
    }
    float* out = g_cb + (size_t)cg * (CSN * CSN);
#pragma unroll
    for (int r = 0; r < 4; r++) {
        int i = ti * 64 + ty * 4 + r;
        int j = tj * 64 + tx * 4;
        *(float4*)&out[(size_t)i * CSN + j] = make_float4(acc[r][0], acc[r][1], acc[r][2], acc[r][3]);
    }
}

// ============================================================
// Y_diag + D*x  -> g_y.   grid (4 i-tiles, 16 chunks, 64 heads), 256 thr
// ============================================================
__global__ __launch_bounds__(256) void k_ydiag(const float* __restrict__ Dv)
{
    int it = blockIdx.x;
    int chunk = blockIdx.y;
    int h = blockIdx.z;
    int g = h >> 3;
    int i0 = it * 64;
    int tid = threadIdx.x;
    int ty = tid >> 4, tx = tid & 15;
    int p0 = tx * 4;

    __shared__ __align__(16) float sx[32][68];
    __shared__ float sM[32][65];
    __shared__ float sdj[32], sdtj[32], sdi[64];

    const float* dac = g_dacs + (size_t)h * TT + chunk * CSN;
    const float* dtp = g_dt   + (size_t)h * TT + chunk * CSN;
    const float* cbp = g_cb + (size_t)(chunk * 8 + g) * (CSN * CSN);

    if (tid < 64) sdi[tid] = dac[i0 + tid];
    __syncthreads();

    float acc[4][4];
#pragma unroll
    for (int r = 0; r < 4; r++)
#pragma unroll
        for (int c = 0; c < 4; c++) acc[r][c] = 0.0f;

    float dc_i0 = dac[i0];

    for (int jt = 2 * it + 1; jt >= 0; jt--) {
        int j0 = jt * 32;
        bool overlap = (j0 + 32 > i0);
        if (!overlap) {
            float d = dc_i0 - dac[j0 + 31];
            if (d < DEADTH) break;
        }
        if (tid < 32) { sdj[tid] = dac[j0 + tid]; sdtj[tid] = dtp[j0 + tid]; }
        __syncthreads();
#pragma unroll
        for (int i = 0; i < 2; i++) {
            int f = tid + i * 256;
            int j = f >> 4, pv = (f & 15) * 4;
            *(float4*)&sx[j][pv] =
                *(const float4*)&g_xbc[(size_t)(chunk * CSN + j0 + j) * CONVD + h * PN + pv];
        }
        __syncthreads();
        {
            int im = tid >> 2;
            int jb = (tid & 3) * 8;
            float di = sdi[im];
            int gi = i0 + im;
            float4 cb0 = *(const float4*)&cbp[(size_t)gi * CSN + j0 + jb];
            float4 cb1 = *(const float4*)&cbp[(size_t)gi * CSN + j0 + jb + 4];
            float cbv[8] = {cb0.x, cb0.y, cb0.z, cb0.w, cb1.x, cb1.y, cb1.z, cb1.w};
#pragma unroll
            for (int k = 0; k < 8; k++) {
                int j = jb + k;
                int gj = j0 + j;
                float m = 0.0f;
                if (gj <= gi) {
                    float d = fmaxf(di - sdj[j], -80.0f);
                    m = cbv[k] * __expf(d) * sdtj[j];
                }
                sM[j][im] = m;
            }
        }
        __syncthreads();
#pragma unroll 4
        for (int j = 0; j < 32; j++) {
            float4 xv = *(const float4*)&sx[j][p0];
#pragma unroll
            for (int r = 0; r < 4; r++) {
                float m = sM[j][ty * 4 + r];
                acc[r][0] += m * xv.x;
                acc[r][1] += m * xv.y;
                acc[r][2] += m * xv.z;
                acc[r][3] += m * xv.w;
            }
        }
        __syncthreads();
    }

    float Dh = Dv[h];
#pragma unroll
    for (int r = 0; r < 4; r++) {
        int i = i0 + ty * 4 + r;
        int t = chunk * CSN + i;
        float4 xv = *(const float4*)&g_xbc[(size_t)t * CONVD + h * PN + p0];
        float4 o = make_float4(acc[r][0] + Dh * xv.x, acc[r][1] + Dh * xv.y,
                               acc[r][2] + Dh * xv.z, acc[r][3] + Dh * xv.w);
        *(float4*)&g_y[(size_t)t * INTER + h * PN + p0] = o;
    }
}

// ============================================================
// states kernel
// ============================================================
__global__ __launch_bounds__(256) void k_states()
{
    int chunk = blockIdx.x, h = blockIdx.y, g = h >> 3;
    int tid = threadIdx.x;
    int ty = tid >> 4, tx = tid & 15;
    int p0 = ty * 4, n0 = tx * 8;

    __shared__ __align__(16) float sxw[32][68];
    __shared__ __align__(16) float sB[32][132];
    __shared__ float sw[32];

    const float* dac = g_dacs + (size_t)h * TT + chunk * CSN;
    const float* dtp = g_dt   + (size_t)h * TT + chunk * CSN;
    float dlast = dac[CSN - 1];

    float acc[4][8];
#pragma unroll
    for (int r = 0; r < 4; r++)
#pragma unroll
        for (int c = 0; c < 8; c++) acc[r][c] = 0.0f;

    for (int jt = 7; jt >= 0; jt--) {
        int j0 = jt * 32;
        if (dlast - dac[j0 + 31] < DEADTH) break;
        if (tid < 32)
            sw[tid] = __expf(fmaxf(dlast - dac[j0 + tid], -80.0f)) * dtp[j0 + tid];
        __syncthreads();
#pragma unroll
        for (int i = 0; i < 2; i++) {
            int f = tid + i * 256;
            int j = f >> 4, pv = (f & 15) * 4;
            float4 xv = *(const float4*)&g_xbc[(size_t)(chunk * CSN + j0 + j) * CONVD + h * PN + pv];
            float w = sw[j];
            xv.x *= w; xv.y *= w; xv.z *= w; xv.w *= w;
            *(float4*)&sxw[j][pv] = xv;
        }
#pragma unroll
        for (int i = 0; i < 4; i++) {
            int f = tid + i * 256;
            int j = f >> 5, nv = (f & 31) * 4;
            *(float4*)&sB[j][nv] =
                *(const float4*)&g_xbc[(size_t)(chunk * CSN + j0 + j) * CONVD + INTER + g * NN + nv];
        }
        __syncthreads();
#pragma unroll 2
        for (int j = 0; j < 32; j++) {
            float4 xv = *(const float4*)&sxw[j][p0];
            float4 b0 = *(const float4*)&sB[j][n0];
            float4 b1 = *(const float4*)&sB[j][n0 + 4];
            float xr[4] = {xv.x, xv.y, xv.z, xv.w};
            float bb[8] = {b0.x, b0.y, b0.z, b0.w, b1.x, b1.y, b1.z, b1.w};
#pragma unroll
            for (int r = 0; r < 4; r++)
#pragma unroll
                for (int c = 0; c < 8; c++) acc[r][c] += xr[r] * bb[c];
        }
        __syncthreads();
    }

    float* out = g_state + (size_t)(chunk * HN + h) * (PN * NN);
#pragma unroll
    for (int r = 0; r < 4; r++) {
        *(float4*)&out[(size_t)(p0 + r) * NN + n0]     = make_float4(acc[r][0], acc[r][1], acc[r][2], acc[r][3]);
        *(float4*)&out[(size_t)(p0 + r) * NN + n0 + 4] = make_float4(acc[r][4], acc[r][5], acc[r][6], acc[r][7]);
    }
}

// ============================================================
// inter-chunk scan
// ============================================================
__global__ __launch_bounds__(256) void k_scan()
{
    int b = blockIdx.x, h = blockIdx.y;
    int tid = threadIdx.x;
    float acc[32];
#pragma unroll
    for (int k = 0; k < 32; k++) acc[k] = 0.0f;
    for (int cl = 0; cl < 8; cl++) {
        int chunk = b * 8 + cl;
        size_t base = (size_t)(chunk * HN + h) * (PN * NN);
#pragma unroll
        for (int k = 0; k < 32; k++) g_prev[base + tid + k * 256] = acc[k];
        float decay = __expf(fmaxf(g_dacs[(size_t)h * TT + chunk * CSN + CSN - 1], -80.0f));
#pragma unroll
        for (int k = 0; k < 32; k++)
            acc[k] = decay * acc[k] + g_state[base + tid + k * 256];
    }
}

// ============================================================
// Y_off
// ============================================================
__global__ __launch_bounds__(256) void k_yoff()
{
    int chunk = blockIdx.x;
    if ((chunk & 7) == 0) return;
    int h = blockIdx.y, g = h >> 3;
    const float* dac = g_dacs + (size_t)h * TT + chunk * CSN;
    if (dac[0] < DEADTH) return;

    __shared__ __align__(16) float sPT[128][64];
    __shared__ __align__(16) float sC[16][128];

    int tid = threadIdx.x;
    size_t pbase = (size_t)(chunk * HN + h) * (PN * NN);
#pragma unroll
    for (int k = 0; k < 32; k++) {
        int idx = tid + k * 256;
        int p = idx >> 7, n = idx & 127;
        sPT[n][p] = g_prev[pbase + idx];
    }
    __syncthreads();

    int im = tid >> 4;
    int p0 = (tid & 15) * 4;

    for (int it = 0; it < 16; it++) {
        int i0 = it * 16;
        if (dac[i0] < DEADTH) break;
#pragma unroll
        for (int k = 0; k < 2; k++) {
            int f = tid + k * 256;
            int i = f >> 5, nv = (f & 31) * 4;
            *(float4*)&sC[i][nv] =
                *(const float4*)&g_xbc[(size_t)(chunk * CSN + i0 + i) * CONVD + INTER + GNN + g * NN + nv];
        }
        __syncthreads();
        float4 acc = make_float4(0.f, 0.f, 0.f, 0.f);
#pragma unroll 4
        for (int n = 0; n < 128; n++) {
            float cv = sC[im][n];
            float4 pv = *(const float4*)&sPT[n][p0];
            acc.x += cv * pv.x; acc.y += cv * pv.y;
            acc.z += cv * pv.z; acc.w += cv * pv.w;
        }
        float e = __expf(fmaxf(dac[i0 + im], -80.0f));
        int t = chunk * CSN + i0 + im;
        float4 o = *(float4*)&g_y[(size_t)t * INTER + h * PN + p0];
        o.x += e * acc.x; o.y += e * acc.y; o.z += e * acc.z; o.w += e * acc.w;
        *(float4*)&g_y[(size_t)t * INTER + h * PN + p0] = o;
        __syncthreads();
    }
}

// ============================================================
// RMSNorm * silu(z) gate. Reads g_y (+z from g_zx), writes fp16
// k-permuted g_yh (GEMM2 A operand).
// ============================================================
__global__ __launch_bounds__(256) void k_norm(const float* __restrict__ norm_w)
{
    int t = blockIdx.x;
    int tid = threadIdx.x;
    __shared__ float red[8];
    const float* yp = g_y + (size_t)t * INTER;
    const float* zp = g_zx + (size_t)t * PROJ;
    __half* op = g_yh + (size_t)t * INTER;

    float ss = 0.0f;
#pragma unroll
    for (int k = 0; k < 16; k++) {
        float v = yp[tid + k * 256];
        ss += v * v;
    }
#pragma unroll
    for (int off = 16; off >= 1; off >>= 1) ss += __shfl_xor_sync(0xffffffffu, ss, off);
    if ((tid & 31) == 0) red[tid >> 5] = ss;
    __syncthreads();
    if (tid == 0) {
        float tot = 0.0f;
#pragma unroll
        for (int i = 0; i < 8; i++) tot += red[i];
        red[0] = rsqrtf(tot * (1.0f / INTER) + 1e-5f);
    }
    __syncthreads();
    float rinv = red[0];
#pragma unroll
    for (int k = 0; k < 16; k++) {
        int c = tid + k * 256;
        float v = yp[c];
        float z = zp[c];
        float o = norm_w[c] * v * rinv * siluf(z);
        op[(c & ~31) | kperm(c & 31)] = __float2half_rn(o);
    }
}

// ============================================================
// launch
// ============================================================
extern "C" void kernel_launch(void* const* d_in, const int* in_sizes, int n_in,
                              void* d_out, int out_size)
{
    const float* hidden   = (const float*)d_in[0];
    const float* in_w     = (const float*)d_in[1];
    const float* conv_w   = (const float*)d_in[2];
    const float* conv_b   = (const float*)d_in[3];
    const float* dt_bias  = (const float*)d_in[4];
    const float* A_log    = (const float*)d_in[5];
    const float* Dv       = (const float*)d_in[6];
    const float* norm_w   = (const float*)d_in[7];
    const float* out_w    = (const float*)d_in[8];
    float* outp = (float*)d_out;

    float*  zx;  cudaGetSymbolAddress((void**)&zx,  g_zx);
    __half* ha;  cudaGetSymbolAddress((void**)&ha,  g_ha);
    __half* w1h; cudaGetSymbolAddress((void**)&w1h, g_w1h);
    __half* w2h; cudaGetSymbolAddress((void**)&w2h, g_w2h);
    __half* yh;  cudaGetSymbolAddress((void**)&yh,  g_yh);

    static int smem_set = 0;
    const int gemm_smem = 3 * STGB;   // 92,160 B
    if (!smem_set) {
        cudaFuncSetAttribute(k_gemm, cudaFuncAttributeMaxDynamicSharedMemorySize, gemm_smem);
        smem_set = 1;
    }

    // 0. convert GEMM operands to fp16 (k-block permuted)
    k_cvt<<<2048, 256>>>(hidden, ha,  (TT * HIDD) / 4);
    k_cvt<<<4096, 256>>>(in_w,  w1h, (PROJ * HIDD) / 4);
    k_cvt<<<2048, 256>>>(out_w, w2h, (HIDD * INTER) / 4);

    // 1. in_proj:  zx[T, PROJ] = ha @ w1h^T
    {
        dim3 grid((PROJ + 255) / 256, TT / 128);
        k_gemm<<<grid, 256, gemm_smem>>>(ha, w1h, zx, PROJ, HIDD / 32, HIDD, HIDD, PROJ);
    }
    // 2. conv + silu
    k_conv<<<dim3(CONVD / 256, TT), 256>>>(conv_w, conv_b);
    // 3. dt softplus + cumsum
    k_dtscan<<<dim3(NCH, 8), 256>>>(A_log, dt_bias);
    // 4. CB
    k_cb<<<dim3(16, NCH * GN_), 256>>>();
    // 5. Y_diag + D*x
    k_ydiag<<<dim3(4, NCH, HN), 256>>>(Dv);
    // 6. states
    k_states<<<dim3(NCH, HN), 256>>>();
    // 7. scan
    k_scan<<<dim3(BB, HN), 256>>>();
    // 8. Y_off
    k_yoff<<<dim3(NCH, HN), 256>>>();
    // 9. rmsnorm + gate -> fp16 permuted y
    k_norm<<<TT, 256>>>(norm_w);
    // 10. out_proj: out[T, HIDD] = yh @ w2h^T
    {
        dim3 grid(HIDD / 256, TT / 128);
        k_gemm<<<grid, 256, gemm_smem>>>(yh, w2h, outp, HIDD, INTER / 32, INTER, INTER, HIDD);
    }
    (void)in_sizes; (void)n_in; (void)out_size;
}

// round 16
// speedup vs baseline: 1.8142x; 1.3595x over previous
#include <cuda_runtime.h>
#include <cuda_fp16.h>
#include <cstdint>
#include <math.h>

// ---------------- problem constants ----------------
#define HN     64
#define PN     64
#define GN_    8
#define NN     128
#define CSN    256
#define HIDD   2048
#define INTER  4096
#define GNN    1024
#define CONVD  6144
#define PROJ   10304
#define PROJP  10496   // PROJ padded to 41*256
#define LL     2048
#define BB     2
#define TT     4096
#define NCH    16
#define DEADTH (-40.0f)

// ---------------- scratch ----------------
__device__ float g_zx   [(size_t)TT * PROJ];
__device__ float g_xbc  [(size_t)TT * CONVD];
__device__ float g_dt   [(size_t)HN * TT];
__device__ float g_dacs [(size_t)HN * TT];
__device__ float g_cb   [(size_t)NCH * GN_ * CSN * CSN];
__device__ float g_state[(size_t)NCH * HN * PN * NN];
__device__ float g_prev [(size_t)NCH * HN * PN * NN];
__device__ float g_y    [(size_t)TT * INTER];
// blocked fp16 GEMM operands (slab layout, fragment-permuted + XOR swizzled)
__device__ __align__(16) __half g_ha  [(size_t)TT * HIDD];
__device__ __align__(16) __half g_w1h [(size_t)PROJP * HIDD];
__device__ __align__(16) __half g_w2h [(size_t)HIDD * INTER];
__device__ __align__(16) __half g_yh  [(size_t)TT * INTER];

// ---------------- helpers ----------------
// logical position of k (0..31) within a 32-half row for m16n8k16 fragments
__device__ __host__ __forceinline__ int kperm(int k) {
    return ((k >> 1) & 3) * 8 + ((k >> 4) & 1) * 4 + ((k >> 3) & 1) * 2 + (k & 1);
}
// physical byte offset within a 64B row: XOR-slot swizzle by row&3
__device__ __forceinline__ int physoff(int kl, int row) {
    int p = kperm(kl);
    return ((((p >> 3) + (row & 3)) & 3) * 16) + (p & 7) * 2;
}
__device__ __forceinline__ void mmah(float* c, uint32_t a0, uint32_t a1, uint32_t a2,
                                     uint32_t a3, uint32_t b0, uint32_t b1) {
    asm volatile(
        "mma.sync.aligned.m16n8k16.row.col.f32.f16.f16.f32 "
        "{%0,%1,%2,%3},{%4,%5,%6,%7},{%8,%9},{%0,%1,%2,%3};\n"
        : "+f"(c[0]), "+f"(c[1]), "+f"(c[2]), "+f"(c[3])
        : "r"(a0), "r"(a1), "r"(a2), "r"(a3), "r"(b0), "r"(b1));
}
__device__ __forceinline__ void bulkcp(uint32_t sdst, const void* gsrc, uint32_t bytes,
                                       uint32_t mbar) {
    asm volatile(
        "cp.async.bulk.shared::cluster.global.mbarrier::complete_tx::bytes "
        "[%0], [%1], %2, [%3];"
        :: "r"(sdst), "l"(gsrc), "r"(bytes), "r"(mbar) : "memory");
}
#define MBAR_INIT(a, c) \
    asm volatile("mbarrier.init.shared.b64 [%0], %1;" :: "r"(a), "r"((uint32_t)(c)) : "memory")
#define MBAR_EXPECT_TX(a, b) \
    asm volatile("mbarrier.arrive.expect_tx.shared.b64 _, [%0], %1;" \
                 :: "r"(a), "r"((uint32_t)(b)) : "memory")
#define MBAR_WAIT(a, par) do { \
    uint32_t _m = (a), _p = (par), _d; \
    asm volatile("{\n\t.reg .pred p;\n\t" \
        "mbarrier.try_wait.parity.acquire.cta.shared::cta.b64 p, [%1], %2;\n\t" \
        "selp.b32 %0, 1, 0, p;\n\t}" : "=r"(_d) : "r"(_m), "r"(_p) : "memory"); \
    if (!_d) { \
        asm volatile("{\n\t.reg .pred P1;\n\tW_%=:\n\t" \
            "mbarrier.try_wait.parity.acquire.cta.shared::cta.b64 P1, [%0], %1, 0x989680;\n\t" \
            "@P1 bra.uni D_%=;\n\tbra.uni W_%=;\n\tD_%=:\n\t}" \
            :: "r"(_m), "r"(_p) : "memory"); \
    } \
} while (0)

__device__ __forceinline__ float siluf(float v) { return v / (1.0f + __expf(-v)); }
__device__ __forceinline__ float softplusf(float x) {
    return (x > 20.0f) ? x : log1pf(__expf(x));
}

// ============================================================
// fp16 GEMM: C[M,Nn] = A[M,K] * B[Nn,K]^T, blocked slab operands.
// A slabs: (row-block 128) x (k-tile 32) = 8192B, smem image.
// B slabs: (row-block 256) x (k-tile 32) = 16384B.
// 4-stage cp.async.bulk ring, one issuing thread, mbarrier sync.
// ============================================================
#define STG 24576
__global__ __launch_bounds__(256) void k_gemm(
    const __half* __restrict__ Ab, const __half* __restrict__ Bb, float* __restrict__ C,
    int Nn, int nk, int ldc)
{
    extern __shared__ char smc[];
    const int tid  = threadIdx.x;
    const int lane = tid & 31;
    const int warp = tid >> 5;
    const int wm   = warp >> 2;
    const int wn   = warp & 3;
    const int bm0  = blockIdx.y * 128;
    const int bn0  = blockIdx.x * 256;

    const char* Ag = (const char*)Ab + (size_t)blockIdx.y * nk * 8192;
    const char* Bg = (const char*)Bb + (size_t)blockIdx.x * nk * 16384;

    const uint32_t smb = (uint32_t)__cvta_generic_to_shared(smc);
    const uint32_t mb  = smb + 4 * STG;

    if (tid == 0) {
        MBAR_INIT(mb + 0,  1);
        MBAR_INIT(mb + 8,  1);
        MBAR_INIT(mb + 16, 1);
        MBAR_INIT(mb + 24, 1);
    }
    __syncthreads();

    auto issue = [&](int kt) {
        uint32_t s = smb + (uint32_t)(kt & 3) * STG;
        uint32_t m = mb + (uint32_t)(kt & 3) * 8;
        MBAR_EXPECT_TX(m, 24576);
        bulkcp(s,        Ag + (size_t)kt * 8192,  8192,  m);
        bulkcp(s + 8192, Bg + (size_t)kt * 16384, 16384, m);
    };
    if (tid == 0) { issue(0); issue(1); issue(2); }

    // fragment bases (conflict-free XOR swizzle)
    const int g = lane >> 2, t = lane & 3;
    const int sw = ((t + (g & 3)) & 3) * 16;
    const char* aB = smc + (wm * 64 + g) * 64 + sw;
    const char* bB = smc + 8192 + (wn * 64 + g) * 64 + sw;

    float acc[4][8][4];
#pragma unroll
    for (int i = 0; i < 4; i++)
#pragma unroll
        for (int j = 0; j < 8; j++)
#pragma unroll
            for (int k = 0; k < 4; k++) acc[i][j][k] = 0.0f;

    for (int kt = 0; kt < nk; kt++) {
        const int s = kt & 3;
        MBAR_WAIT(mb + s * 8, (uint32_t)((kt >> 2) & 1));

        const char* a_ = aB + s * STG;
        const char* b_ = bB + s * STG;

        uint4 av0[4], av1[4], bv[8];
#pragma unroll
        for (int mi = 0; mi < 4; mi++) {
            av0[mi] = *(const uint4*)(a_ + mi * 1024);        // row mi*16+g
            av1[mi] = *(const uint4*)(a_ + mi * 1024 + 512);  // row mi*16+8+g
        }
#pragma unroll
        for (int ni = 0; ni < 8; ni++)
            bv[ni] = *(const uint4*)(b_ + ni * 512);          // col ni*8+g

#pragma unroll
        for (int mi = 0; mi < 4; mi++)
#pragma unroll
            for (int ni = 0; ni < 8; ni++)
                mmah(acc[mi][ni], av0[mi].x, av1[mi].x, av0[mi].y, av1[mi].y,
                     bv[ni].x, bv[ni].y);
#pragma unroll
        for (int mi = 0; mi < 4; mi++)
#pragma unroll
            for (int ni = 0; ni < 8; ni++)
                mmah(acc[mi][ni], av0[mi].z, av1[mi].z, av0[mi].w, av1[mi].w,
                     bv[ni].z, bv[ni].w);

        __syncthreads();
        if (tid == 0 && kt + 3 < nk) issue(kt + 3);
    }

    // epilogue
#pragma unroll
    for (int mi = 0; mi < 4; mi++) {
#pragma unroll
        for (int ni = 0; ni < 8; ni++) {
            int row = bm0 + wm * 64 + mi * 16 + g;
            int col = bn0 + wn * 64 + ni * 8 + t * 2;
            if (col < Nn) {
                *(float2*)&C[(size_t)row * ldc + col] =
                    make_float2(acc[mi][ni][0], acc[mi][ni][1]);
                *(float2*)&C[(size_t)(row + 8) * ldc + col] =
                    make_float2(acc[mi][ni][2], acc[mi][ni][3]);
            }
        }
    }
}

// ============================================================
// float -> fp16 blocked conversion.
// in: [R x K] row-major. out: slabs of (BR rows x 32 k), smem image.
// klog = log2(K); brlog = log2(BR); nk = K/32.
// ============================================================
__global__ __launch_bounds__(256) void k_cvt_blk(
    const float* __restrict__ in, __half* __restrict__ out, int n4,
    int klog, int brlog, int nk)
{
    int i = blockIdx.x * 256 + threadIdx.x;
    int stride = gridDim.x * 256;
    const int kmask = (1 << klog) - 1;
    const int brmask = (1 << brlog) - 1;
    for (; i < n4; i += stride) {
        int idx = i * 4;
        float4 v = *(const float4*)&in[(size_t)idx];
        int row = idx >> klog;
        int k   = idx & kmask;
        size_t slab = (((size_t)(row >> brlog) * nk) + (k >> 5)) << (6 + brlog);
        char* base = (char*)out + slab + (size_t)(row & brmask) * 64;
        float vv[4] = {v.x, v.y, v.z, v.w};
#pragma unroll
        for (int j = 0; j < 4; j++)
            *(__half*)(base + physoff((k + j) & 31, row)) = __float2half_rn(vv[j]);
    }
}

// ============================================================
// conv1d + silu
// ============================================================
__global__ __launch_bounds__(256) void k_conv(
    const float* __restrict__ conv_w, const float* __restrict__ conv_b)
{
    int c = blockIdx.x * 256 + threadIdx.x;
    int t = blockIdx.y;
    int lt = t & (LL - 1);
    float w0 = conv_w[c * 4 + 0], w1 = conv_w[c * 4 + 1];
    float w2 = conv_w[c * 4 + 2], w3 = conv_w[c * 4 + 3];
    const float* zp = g_zx + (size_t)t * PROJ + INTER + c;
    float v = conv_b[c];
    if (lt >= 3) v += w0 * zp[-3 * (ptrdiff_t)PROJ];
    if (lt >= 2) v += w1 * zp[-2 * (ptrdiff_t)PROJ];
    if (lt >= 1) v += w2 * zp[-1 * (ptrdiff_t)PROJ];
    v += w3 * zp[0];
    g_xbc[(size_t)t * CONVD + c] = siluf(v);
}

// ============================================================
// dt softplus + per-chunk cumsum
// ============================================================
__global__ __launch_bounds__(256) void k_dtscan(
    const float* __restrict__ A_log, const float* __restrict__ dt_bias)
{
    int warp = threadIdx.x >> 5, lane = threadIdx.x & 31;
    int h = blockIdx.y * 8 + warp;
    int chunk = blockIdx.x;
    float Ah = -__expf(A_log[h]);
    float bias = dt_bias[h];
    int tbase = chunk * CSN + lane * 8;

    float pre[8];
    float run = 0.0f;
    float dts[8];
#pragma unroll
    for (int k = 0; k < 8; k++) {
        float raw = g_zx[(size_t)(tbase + k) * PROJ + (INTER + CONVD) + h];
        float dt = softplusf(raw + bias);
        dts[k] = dt;
        run += dt * Ah;
        pre[k] = run;
    }
    float tot = run;
#pragma unroll
    for (int off = 1; off < 32; off <<= 1) {
        float n = __shfl_up_sync(0xffffffffu, tot, off);
        if (lane >= off) tot += n;
    }
    float excl = tot - run;
#pragma unroll
    for (int k = 0; k < 8; k++) {
        g_dt  [(size_t)h * TT + tbase + k] = dts[k];
        g_dacs[(size_t)h * TT + tbase + k] = pre[k] + excl;
    }
}

// ============================================================
// CB (lower-triangular 64x64 tiles)
// ============================================================
__global__ __launch_bounds__(256) void k_cb()
{
    int tile = blockIdx.x;
    int ti = tile >> 2, tj = tile & 3;
    if (ti < tj) return;
    int cg = blockIdx.y;
    int chunk = cg >> 3, g = cg & 7;

    __shared__ float sC[64][33];
    __shared__ float sB[64][33];

    int tid = threadIdx.x;
    int ty = tid >> 4, tx = tid & 15;
    float acc[4][4];
#pragma unroll
    for (int r = 0; r < 4; r++)
#pragma unroll
        for (int c = 0; c < 4; c++) acc[r][c] = 0.0f;

    const size_t cBase = (size_t)(chunk * CSN) * CONVD + INTER + GNN + (size_t)g * NN;
    const size_t bBase = (size_t)(chunk * CSN) * CONVD + INTER + (size_t)g * NN;

    for (int kt = 0; kt < 4; kt++) {
        int k0 = kt * 32;
#pragma unroll
        for (int i = 0; i < 2; i++) {
            int f = tid + i * 256;
            int r = f >> 3, kv = (f & 7) * 4;
            float4 cv = *(const float4*)&g_xbc[cBase + (size_t)(ti * 64 + r) * CONVD + k0 + kv];
            float4 bv = *(const float4*)&g_xbc[bBase + (size_t)(tj * 64 + r) * CONVD + k0 + kv];
            sC[r][kv + 0] = cv.x; sC[r][kv + 1] = cv.y;
            sC[r][kv + 2] = cv.z; sC[r][kv + 3] = cv.w;
            sB[r][kv + 0] = bv.x; sB[r][kv + 1] = bv.y;
            sB[r][kv + 2] = bv.z; sB[r][kv + 3] = bv.w;
        }
        __syncthreads();
#pragma unroll
        for (int kk = 0; kk < 32; kk++) {
            float a[4], b[4];
#pragma unroll
            for (int r = 0; r < 4; r++) a[r] = sC[ty * 4 + r][kk];
#pragma unroll
            for (int c = 0; c < 4; c++) b[c] = sB[tx * 4 + c][kk];
#pragma unroll
            for (int r = 0; r < 4; r++)
#pragma unroll
                for (int c = 0; c < 4; c++) acc[r][c] += a[r] * b[c];
        }
        __syncthreads();
    }
    float* out = g_cb + (size_t)cg * (CSN * CSN);
#pragma unroll
    for (int r = 0; r < 4; r++) {
        int i = ti * 64 + ty * 4 + r;
        int j = tj * 64 + tx * 4;
        *(float4*)&out[(size_t)i * CSN + j] = make_float4(acc[r][0], acc[r][1], acc[r][2], acc[r][3]);
    }
}

// ============================================================
// Y_diag + D*x
// ============================================================
__global__ __launch_bounds__(256) void k_ydiag(const float* __restrict__ Dv)
{
    int it = blockIdx.x;
    int chunk = blockIdx.y;
    int h = blockIdx.z;
    int g = h >> 3;
    int i0 = it * 64;
    int tid = threadIdx.x;
    int ty = tid >> 4, tx = tid & 15;
    int p0 = tx * 4;

    __shared__ __align__(16) float sx[32][68];
    __shared__ float sM[32][65];
    __shared__ float sdj[32], sdtj[32], sdi[64];

    const float* dac = g_dacs + (size_t)h * TT + chunk * CSN;
    const float* dtp = g_dt   + (size_t)h * TT + chunk * CSN;
    const float* cbp = g_cb + (size_t)(chunk * 8 + g) * (CSN * CSN);

    if (tid < 64) sdi[tid] = dac[i0 + tid];
    __syncthreads();

    float acc[4][4];
#pragma unroll
    for (int r = 0; r < 4; r++)
#pragma unroll
        for (int c = 0; c < 4; c++) acc[r][c] = 0.0f;

    float dc_i0 = dac[i0];

    for (int jt = 2 * it + 1; jt >= 0; jt--) {
        int j0 = jt * 32;
        bool overlap = (j0 + 32 > i0);
        if (!overlap) {
            float d = dc_i0 - dac[j0 + 31];
            if (d < DEADTH) break;
        }
        if (tid < 32) { sdj[tid] = dac[j0 + tid]; sdtj[tid] = dtp[j0 + tid]; }
        __syncthreads();
#pragma unroll
        for (int i = 0; i < 2; i++) {
            int f = tid + i * 256;
            int j = f >> 4, pv = (f & 15) * 4;
            *(float4*)&sx[j][pv] =
                *(const float4*)&g_xbc[(size_t)(chunk * CSN + j0 + j) * CONVD + h * PN + pv];
        }
        __syncthreads();
        {
            int im = tid >> 2;
            int jb = (tid & 3) * 8;
            float di = sdi[im];
            int gi = i0 + im;
            float4 cb0 = *(const float4*)&cbp[(size_t)gi * CSN + j0 + jb];
            float4 cb1 = *(const float4*)&cbp[(size_t)gi * CSN + j0 + jb + 4];
            float cbv[8] = {cb0.x, cb0.y, cb0.z, cb0.w, cb1.x, cb1.y, cb1.z, cb1.w};
#pragma unroll
            for (int k = 0; k < 8; k++) {
                int j = jb + k;
                int gj = j0 + j;
                float m = 0.0f;
                if (gj <= gi) {
                    float d = fmaxf(di - sdj[j], -80.0f);
                    m = cbv[k] * __expf(d) * sdtj[j];
                }
                sM[j][im] = m;
            }
        }
        __syncthreads();
#pragma unroll 4
        for (int j = 0; j < 32; j++) {
            float4 xv = *(const float4*)&sx[j][p0];
#pragma unroll
            for (int r = 0; r < 4; r++) {
                float m = sM[j][ty * 4 + r];
                acc[r][0] += m * xv.x;
                acc[r][1] += m * xv.y;
                acc[r][2] += m * xv.z;
                acc[r][3] += m * xv.w;
            }
        }
        __syncthreads();
    }

    float Dh = Dv[h];
#pragma unroll
    for (int r = 0; r < 4; r++) {
        int i = i0 + ty * 4 + r;
        int t = chunk * CSN + i;
        float4 xv = *(const float4*)&g_xbc[(size_t)t * CONVD + h * PN + p0];
        float4 o = make_float4(acc[r][0] + Dh * xv.x, acc[r][1] + Dh * xv.y,
                               acc[r][2] + Dh * xv.z, acc[r][3] + Dh * xv.w);
        *(float4*)&g_y[(size_t)t * INTER + h * PN + p0] = o;
    }
}

// ============================================================
// states kernel
// ============================================================
__global__ __launch_bounds__(256) void k_states()
{
    int chunk = blockIdx.x, h = blockIdx.y, g = h >> 3;
    int tid = threadIdx.x;
    int ty = tid >> 4, tx = tid & 15;
    int p0 = ty * 4, n0 = tx * 8;

    __shared__ __align__(16) float sxw[32][68];
    __shared__ __align__(16) float sB[32][132];
    __shared__ float sw[32];

    const float* dac = g_dacs + (size_t)h * TT + chunk * CSN;
    const float* dtp = g_dt   + (size_t)h * TT + chunk * CSN;
    float dlast = dac[CSN - 1];

    float acc[4][8];
#pragma unroll
    for (int r = 0; r < 4; r++)
#pragma unroll
        for (int c = 0; c < 8; c++) acc[r][c] = 0.0f;

    for (int jt = 7; jt >= 0; jt--) {
        int j0 = jt * 32;
        if (dlast - dac[j0 + 31] < DEADTH) break;
        if (tid < 32)
            sw[tid] = __expf(fmaxf(dlast - dac[j0 + tid], -80.0f)) * dtp[j0 + tid];
        __syncthreads();
#pragma unroll
        for (int i = 0; i < 2; i++) {
            int f = tid + i * 256;
            int j = f >> 4, pv = (f & 15) * 4;
            float4 xv = *(const float4*)&g_xbc[(size_t)(chunk * CSN + j0 + j) * CONVD + h * PN + pv];
            float w = sw[j];
            xv.x *= w; xv.y *= w; xv.z *= w; xv.w *= w;
            *(float4*)&sxw[j][pv] = xv;
        }
#pragma unroll
        for (int i = 0; i < 4; i++) {
            int f = tid + i * 256;
            int j = f >> 5, nv = (f & 31) * 4;
            *(float4*)&sB[j][nv] =
                *(const float4*)&g_xbc[(size_t)(chunk * CSN + j0 + j) * CONVD + INTER + g * NN + nv];
        }
        __syncthreads();
#pragma unroll 2
        for (int j = 0; j < 32; j++) {
            float4 xv = *(const float4*)&sxw[j][p0];
            float4 b0 = *(const float4*)&sB[j][n0];
            float4 b1 = *(const float4*)&sB[j][n0 + 4];
            float xr[4] = {xv.x, xv.y, xv.z, xv.w};
            float bb[8] = {b0.x, b0.y, b0.z, b0.w, b1.x, b1.y, b1.z, b1.w};
#pragma unroll
            for (int r = 0; r < 4; r++)
#pragma unroll
                for (int c = 0; c < 8; c++) acc[r][c] += xr[r] * bb[c];
        }
        __syncthreads();
    }

    float* out = g_state + (size_t)(chunk * HN + h) * (PN * NN);
#pragma unroll
    for (int r = 0; r < 4; r++) {
        *(float4*)&out[(size_t)(p0 + r) * NN + n0]     = make_float4(acc[r][0], acc[r][1], acc[r][2], acc[r][3]);
        *(float4*)&out[(size_t)(p0 + r) * NN + n0 + 4] = make_float4(acc[r][4], acc[r][5], acc[r][6], acc[r][7]);
    }
}

// ============================================================
// inter-chunk scan
// ============================================================
__global__ __launch_bounds__(256) void k_scan()
{
    int b = blockIdx.x, h = blockIdx.y;
    int tid = threadIdx.x;
    float acc[32];
#pragma unroll
    for (int k = 0; k < 32; k++) acc[k] = 0.0f;
    for (int cl = 0; cl < 8; cl++) {
        int chunk = b * 8 + cl;
        size_t base = (size_t)(chunk * HN + h) * (PN * NN);
#pragma unroll
        for (int k = 0; k < 32; k++) g_prev[base + tid + k * 256] = acc[k];
        float decay = __expf(fmaxf(g_dacs[(size_t)h * TT + chunk * CSN + CSN - 1], -80.0f));
#pragma unroll
        for (int k = 0; k < 32; k++)
            acc[k] = decay * acc[k] + g_state[base + tid + k * 256];
    }
}

// ============================================================
// Y_off
// ============================================================
__global__ __launch_bounds__(256) void k_yoff()
{
    int chunk = blockIdx.x;
    if ((chunk & 7) == 0) return;
    int h = blockIdx.y, g = h >> 3;
    const float* dac = g_dacs + (size_t)h * TT + chunk * CSN;
    if (dac[0] < DEADTH) return;

    __shared__ __align__(16) float sPT[128][64];
    __shared__ __align__(16) float sC[16][128];

    int tid = threadIdx.x;
    size_t pbase = (size_t)(chunk * HN + h) * (PN * NN);
#pragma unroll
    for (int k = 0; k < 32; k++) {
        int idx = tid + k * 256;
        int p = idx >> 7, n = idx & 127;
        sPT[n][p] = g_prev[pbase + idx];
    }
    __syncthreads();

    int im = tid >> 4;
    int p0 = (tid & 15) * 4;

    for (int it = 0; it < 16; it++) {
        int i0 = it * 16;
        if (dac[i0] < DEADTH) break;
#pragma unroll
        for (int k = 0; k < 2; k++) {
            int f = tid + k * 256;
            int i = f >> 5, nv = (f & 31) * 4;
            *(float4*)&sC[i][nv] =
                *(const float4*)&g_xbc[(size_t)(chunk * CSN + i0 + i) * CONVD + INTER + GNN + g * NN + nv];
        }
        __syncthreads();
        float4 acc = make_float4(0.f, 0.f, 0.f, 0.f);
#pragma unroll 4
        for (int n = 0; n < 128; n++) {
            float cv = sC[im][n];
            float4 pv = *(const float4*)&sPT[n][p0];
            acc.x += cv * pv.x; acc.y += cv * pv.y;
            acc.z += cv * pv.z; acc.w += cv * pv.w;
        }
        float e = __expf(fmaxf(dac[i0 + im], -80.0f));
        int t = chunk * CSN + i0 + im;
        float4 o = *(float4*)&g_y[(size_t)t * INTER + h * PN + p0];
        o.x += e * acc.x; o.y += e * acc.y; o.z += e * acc.z; o.w += e * acc.w;
        *(float4*)&g_y[(size_t)t * INTER + h * PN + p0] = o;
        __syncthreads();
    }
}

// ============================================================
// RMSNorm * silu(z) gate -> blocked fp16 g_yh (GEMM2 A operand)
// ============================================================
__global__ __launch_bounds__(256) void k_norm(const float* __restrict__ norm_w)
{
    int t = blockIdx.x;
    int tid = threadIdx.x;
    __shared__ float red[8];
    const float* yp = g_y + (size_t)t * INTER;
    const float* zp = g_zx + (size_t)t * PROJ;

    float ss = 0.0f;
#pragma unroll
    for (int k = 0; k < 16; k++) {
        float v = yp[tid + k * 256];
        ss += v * v;
    }
#pragma unroll
    for (int off = 16; off >= 1; off >>= 1) ss += __shfl_xor_sync(0xffffffffu, ss, off);
    if ((tid & 31) == 0) red[tid >> 5] = ss;
    __syncthreads();
    if (tid == 0) {
        float tot = 0.0f;
#pragma unroll
        for (int i = 0; i < 8; i++) tot += red[i];
        red[0] = rsqrtf(tot * (1.0f / INTER) + 1e-5f);
    }
    __syncthreads();
    float rinv = red[0];
    // blocked layout: row = t (BR=128), K = INTER (nk = 128)
    char* obase = (char*)g_yh + (((size_t)(t >> 7) * 128) << 13) + (size_t)(t & 127) * 64;
#pragma unroll
    for (int k = 0; k < 16; k++) {
        int c = tid + k * 256;
        float v = yp[c];
        float z = zp[c];
        float o = norm_w[c] * v * rinv * siluf(z);
        *(__half*)(obase + (size_t)(c >> 5) * 8192 + physoff(c & 31, t)) = __float2half_rn(o);
    }
}

// ============================================================
// launch
// ============================================================
extern "C" void kernel_launch(void* const* d_in, const int* in_sizes, int n_in,
                              void* d_out, int out_size)
{
    const float* hidden   = (const float*)d_in[0];
    const float* in_w     = (const float*)d_in[1];
    const float* conv_w   = (const float*)d_in[2];
    const float* conv_b   = (const float*)d_in[3];
    const float* dt_bias  = (const float*)d_in[4];
    const float* A_log    = (const float*)d_in[5];
    const float* Dv       = (const float*)d_in[6];
    const float* norm_w   = (const float*)d_in[7];
    const float* out_w    = (const float*)d_in[8];
    float* outp = (float*)d_out;

    float*  zx;  cudaGetSymbolAddress((void**)&zx,  g_zx);
    __half* ha;  cudaGetSymbolAddress((void**)&ha,  g_ha);
    __half* w1h; cudaGetSymbolAddress((void**)&w1h, g_w1h);
    __half* w2h; cudaGetSymbolAddress((void**)&w2h, g_w2h);
    __half* yh;  cudaGetSymbolAddress((void**)&yh,  g_yh);

    static int smem_set = 0;
    const int gemm_smem = 4 * STG + 64;   // 98,368 B
    if (!smem_set) {
        cudaFuncSetAttribute(k_gemm, cudaFuncAttributeMaxDynamicSharedMemorySize, gemm_smem);
        smem_set = 1;
    }

    // 0. convert GEMM operands to blocked fp16
    //    hidden: [4096 x 2048], BR=128 (A of GEMM1)
    k_cvt_blk<<<2048, 256>>>(hidden, ha,  (TT * HIDD) / 4,  11, 7, 64);
    //    in_w:   [10304 x 2048], BR=256 (B of GEMM1; pad rows garbage-ok)
    k_cvt_blk<<<4096, 256>>>(in_w,  w1h, (PROJ * HIDD) / 4, 11, 8, 64);
    //    out_w:  [2048 x 4096], BR=256 (B of GEMM2)
    k_cvt_blk<<<2048, 256>>>(out_w, w2h, (HIDD * INTER) / 4, 12, 8, 128);

    // 1. in_proj:  zx[T, PROJ] = ha @ w1h^T
    {
        dim3 grid(PROJP / 256, TT / 128);
        k_gemm<<<grid, 256, gemm_smem>>>(ha, w1h, zx, PROJ, HIDD / 32, PROJ);
    }
    // 2. conv + silu
    k_conv<<<dim3(CONVD / 256, TT), 256>>>(conv_w, conv_b);
    // 3. dt softplus + cumsum
    k_dtscan<<<dim3(NCH, 8), 256>>>(A_log, dt_bias);
    // 4. CB
    k_cb<<<dim3(16, NCH * GN_), 256>>>();
    // 5. Y_diag + D*x
    k_ydiag<<<dim3(4, NCH, HN), 256>>>(Dv);
    // 6. states
    k_states<<<dim3(NCH, HN), 256>>>();
    // 7. scan
    k_scan<<<dim3(BB, HN), 256>>>();
    // 8. Y_off
    k_yoff<<<dim3(NCH, HN), 256>>>();
    // 9. rmsnorm + gate -> blocked fp16 y
    k_norm<<<TT, 256>>>(norm_w);
    // 10. out_proj: out[T, HIDD] = yh @ w2h^T
    {
        dim3 grid(HIDD / 256, TT / 128);
        k_gemm<<<grid, 256, gemm_smem>>>(yh, w2h, outp, HIDD, INTER / 32, HIDD);
    }
    (void)in_sizes; (void)n_in; (void)out_size;
}